// round 13
// baseline (speedup 1.0000x reference)
#include <cuda_runtime.h>
#include <cuda_bf16.h>
#include <cuda_fp16.h>
#include <cstdint>

#define N_NODES 4096
#define IN_F 512
#define OUT_F 64
#define HEADS 8
#define ALPHA 0.2f

#define RT 128                 // rows per CTA (wh kernel)
#define KC 32                  // k per chunk (wh kernel)
#define NCH_W (IN_F / KC)      // 16 chunks (wh)
#define ASTR 40                // padded bf16 row stride (80 B) (wh kernel)
#define BSTR 40

// ---- wh dynamic smem offsets ----
#define WH_A(buf, prec) ((buf) * 20480 + (prec) * 10240)
#define WH_B(buf, prec) (40960 + (buf) * 10240 + (prec) * 5120)
#define WH_T 0                  // epilogue transpose tile [64][136] fp16 (17408 B)
#define WH_AV 18432             // epilogue a1/a2 staging (128 floats)
#define WH_SMEM 61440

// ---- gat (fp16, 128x64 tile, 512 threads, KC2=128, smem tables) ----
#define GAT_RT 128
#define KC2 128
#define NCH2 (N_NODES / KC2)   // 32 chunks
#define AST2 136               // fp16 stride (272 B) for A and B tiles
#define GA_A(buf) ((buf) * 34816)            // [128][136] fp16, 2 bufs
#define GA_B(buf) (69632 + (buf) * 17408)    // [64][136] fp16, 2 bufs
#define GA_T(tb)  (104448 + (tb) * 1536)     // [3 tables][128] float, 3 bufs
#define GA_DSH 109056                        // 512 floats
#define GA_SMEM 111616

// ---------------- scratch (device globals; no allocation) ----------------
__device__ __align__(16) float g_Wh[HEADS * N_NODES * OUT_F];          // 8 MB [h][n][o]
__device__ float g_f1[HEADS * N_NODES];
__device__ float g_f2[HEADS * N_NODES];
__device__ float g_P1[HEADS * N_NODES];   // exp(f1 - M)  (shifted)
__device__ float g_P2[HEADS * N_NODES];   // exp(f2)
__device__ float g_Q1[HEADS * N_NODES];   // exp(a*f1 - M)
__device__ float g_Q2[HEADS * N_NODES];   // exp(a*f2)
__device__ float g_mx[HEADS];             // per-head max f2
__device__ unsigned g_adjbits[N_NODES * (N_NODES / 32)];               // 2 MB
__device__ __align__(16) __half g_WhT_h16[HEADS * OUT_F * N_NODES];    // 4 MB [h][o][m]
__device__ __align__(16) __nv_bfloat16 g_x_hi[N_NODES * IN_F];         // 4 MB [n][k]
__device__ __align__(16) __nv_bfloat16 g_x_lo[N_NODES * IN_F];
__device__ __align__(16) __nv_bfloat16 g_WT_hi[HEADS * OUT_F * IN_F];  // 512 KB [h][o][k]
__device__ __align__(16) __nv_bfloat16 g_WT_lo[HEADS * OUT_F * IN_F];

// ---------------- helpers ----------------
__device__ __forceinline__ uint32_t smem_u32(const void* p) {
    uint32_t a;
    asm("{ .reg .u64 t; cvta.to.shared.u64 t, %1; cvt.u32.u64 %0, t; }" : "=r"(a) : "l"(p));
    return a;
}
__device__ __forceinline__ void cp16(uint32_t dst, const void* src) {
    asm volatile("cp.async.cg.shared.global [%0], [%1], 16;" :: "r"(dst), "l"(src) : "memory");
}
__device__ __forceinline__ void cp_commit() {
    asm volatile("cp.async.commit_group;" ::: "memory");
}
template <int N>
__device__ __forceinline__ void cp_wait() {
    asm volatile("cp.async.wait_group %0;" :: "n"(N) : "memory");
}
__device__ __forceinline__ void ldm4(uint32_t* r, uint32_t addr) {
    asm volatile("ldmatrix.sync.aligned.m8n8.x4.shared.b16 {%0,%1,%2,%3}, [%4];"
                 : "=r"(r[0]), "=r"(r[1]), "=r"(r[2]), "=r"(r[3]) : "r"(addr) : "memory");
}
__device__ __forceinline__ void mma_bf16(float* c, const uint32_t* a, uint32_t b0,
                                         uint32_t b1) {
    asm("mma.sync.aligned.m16n8k16.row.col.f32.bf16.bf16.f32 "
        "{%0,%1,%2,%3}, {%4,%5,%6,%7}, {%8,%9}, {%0,%1,%2,%3};"
        : "+f"(c[0]), "+f"(c[1]), "+f"(c[2]), "+f"(c[3])
        : "r"(a[0]), "r"(a[1]), "r"(a[2]), "r"(a[3]), "r"(b0), "r"(b1));
}
__device__ __forceinline__ void mma_f16(float* c, const uint32_t* a, uint32_t b0,
                                        uint32_t b1) {
    asm("mma.sync.aligned.m16n8k16.row.col.f32.f16.f16.f32 "
        "{%0,%1,%2,%3}, {%4,%5,%6,%7}, {%8,%9}, {%0,%1,%2,%3};"
        : "+f"(c[0]), "+f"(c[1]), "+f"(c[2]), "+f"(c[3])
        : "r"(a[0]), "r"(a[1]), "r"(a[2]), "r"(a[3]), "r"(b0), "r"(b1));
}
__device__ __forceinline__ void split_pair(float x, float y, unsigned& hi, unsigned& lo) {
    __nv_bfloat162 h2 = __float22bfloat162_rn(make_float2(x, y));
    float2 hf = __bfloat1622float2(h2);
    __nv_bfloat162 l2 = __float22bfloat162_rn(make_float2(x - hf.x, y - hf.y));
    hi = *reinterpret_cast<unsigned*>(&h2);
    lo = *reinterpret_cast<unsigned*>(&l2);
}

// ---------------- kernel: fused prep (bitpack | xsplit | wsplit) ----------------
__global__ __launch_bounds__(256) void prep_kernel(const int* __restrict__ adj,
                                                   const float* __restrict__ x,
                                                   const float* __restrict__ W) {
    const int b = blockIdx.x;
    const int tid = threadIdx.x;
    if (b < 2048) {
        int t = b * 256 + tid;
        const int4* p = (const int4*)adj + (size_t)t * 8;
        unsigned w = 0;
#pragma unroll
        for (int i = 0; i < 8; i++) {
            int4 v = p[i];
            w |= (v.x > 0 ? 1u : 0u) << (4 * i);
            w |= (v.y > 0 ? 1u : 0u) << (4 * i + 1);
            w |= (v.z > 0 ? 1u : 0u) << (4 * i + 2);
            w |= (v.w > 0 ? 1u : 0u) << (4 * i + 3);
        }
        g_adjbits[t] = w;
    } else if (b < 3072) {
        int gid = (b - 2048) * 256 + tid;
        const float4* xp = (const float4*)x + gid * 2;
        float4 v0 = xp[0], v1 = xp[1];
        float f[8] = {v0.x, v0.y, v0.z, v0.w, v1.x, v1.y, v1.z, v1.w};
        unsigned hw[4], lw[4];
#pragma unroll
        for (int i = 0; i < 4; i++) split_pair(f[2 * i], f[2 * i + 1], hw[i], lw[i]);
        *(uint4*)(g_x_hi + (size_t)gid * 8) = make_uint4(hw[0], hw[1], hw[2], hw[3]);
        *(uint4*)(g_x_lo + (size_t)gid * 8) = make_uint4(lw[0], lw[1], lw[2], lw[3]);
    } else {
        const int h = b - 3072;
#pragma unroll 4
        for (int i = 0; i < 128; i++) {
            int lin = i * 256 + tid;
            int o = lin >> 9, k = lin & 511;
            float v = W[((size_t)h * IN_F + k) * OUT_F + o];
            __nv_bfloat16 hb = __float2bfloat16(v);
            __nv_bfloat16 lb = __float2bfloat16(v - __bfloat162float(hb));
            size_t d = ((size_t)h * OUT_F + o) * IN_F + k;
            g_WT_hi[d] = hb;
            g_WT_lo[d] = lb;
        }
    }
}

// ---------------- kernel: Wh = x @ W via HMMA + fused f1/f2/exp/WhT epilogue ----------------
__global__ __launch_bounds__(256, 2) void wh_mma_kernel(const float* __restrict__ a1v,
                                                        const float* __restrict__ a2v) {
    extern __shared__ __align__(16) char sm[];
    const int t = threadIdx.x;
    const int wid = t >> 5, lane = t & 31;
    const int h = blockIdx.y;
    const int nbase = blockIdx.x * RT;

    const int a_p[4] = {(t * 4) >> 9, (t * 4 + 1) >> 9, (t * 4 + 2) >> 9, (t * 4 + 3) >> 9};
    int a_r[4], a_q[4];
    const __nv_bfloat16* a_src[4];
    uint32_t a_doff[4];
#pragma unroll
    for (int i = 0; i < 4; i++) {
        int idx = t * 4 + i;
        a_r[i] = (idx >> 2) & 127;
        a_q[i] = idx & 3;
        a_src[i] = (a_p[i] ? g_x_lo : g_x_hi) + (size_t)(nbase + a_r[i]) * IN_F + a_q[i] * 8;
        a_doff[i] = (uint32_t)(a_r[i] * (ASTR * 2) + a_q[i] * 16);
    }
    int b_p[2];
    const __nv_bfloat16* b_src[2];
    uint32_t b_doff[2];
#pragma unroll
    for (int i = 0; i < 2; i++) {
        int idx = t * 2 + i;
        b_p[i] = idx >> 8;
        int br = (idx >> 2) & 63, bq = idx & 3;
        b_src[i] = (b_p[i] ? g_WT_lo : g_WT_hi) + ((size_t)h * OUT_F + br) * IN_F + bq * 8;
        b_doff[i] = (uint32_t)(br * (BSTR * 2) + bq * 16);
    }
    const uint32_t smb = smem_u32(sm);

#pragma unroll
    for (int i = 0; i < 4; i++) cp16(smb + WH_A(0, a_p[i]) + a_doff[i], a_src[i]);
#pragma unroll
    for (int i = 0; i < 2; i++) cp16(smb + WH_B(0, b_p[i]) + b_doff[i], b_src[i]);
    cp_commit();

    float acc[8][4];
#pragma unroll
    for (int j = 0; j < 8; j++)
#pragma unroll
        for (int q = 0; q < 4; q++) acc[j][q] = 0.f;

    const uint32_t aRow = (16 * wid + (lane & 15)) * (ASTR * 2) + (lane >> 4) * 16;
    const uint32_t bRow = (lane & 7) * (BSTR * 2) + (lane >> 3) * 16;

    for (int c = 0; c < NCH_W; c++) {
        const int p = c & 1, pn = p ^ 1;
        cp_wait<0>();
        __syncthreads();
        if (c + 1 < NCH_W) {
            const int kb = (c + 1) * KC;
#pragma unroll
            for (int i = 0; i < 4; i++) cp16(smb + WH_A(pn, a_p[i]) + a_doff[i], a_src[i] + kb);
#pragma unroll
            for (int i = 0; i < 2; i++) cp16(smb + WH_B(pn, b_p[i]) + b_doff[i], b_src[i] + kb);
            cp_commit();
        }
        uint32_t afh[2][4], afl[2][4];
        ldm4(afh[0], smb + WH_A(p, 0) + aRow);
        ldm4(afh[1], smb + WH_A(p, 0) + aRow + 32);
        ldm4(afl[0], smb + WH_A(p, 1) + aRow);
        ldm4(afl[1], smb + WH_A(p, 1) + aRow + 32);
#pragma unroll
        for (int j = 0; j < 8; j++) {
            uint32_t bh[4], bl[4];
            ldm4(bh, smb + WH_B(p, 0) + j * 8 * (BSTR * 2) + bRow);
            ldm4(bl, smb + WH_B(p, 1) + j * 8 * (BSTR * 2) + bRow);
            mma_bf16(acc[j], afh[0], bh[0], bh[1]);
            mma_bf16(acc[j], afh[0], bl[0], bl[1]);
            mma_bf16(acc[j], afl[0], bh[0], bh[1]);
            mma_bf16(acc[j], afh[1], bh[2], bh[3]);
            mma_bf16(acc[j], afh[1], bl[2], bl[3]);
            mma_bf16(acc[j], afl[1], bh[2], bh[3]);
        }
        __syncthreads();
    }

    // ---------- fused epilogue ----------
    const int g = lane >> 2;
    const int c2 = (lane & 3) * 2;
    const int row0 = nbase + 16 * wid + g;
    const int row1 = row0 + 8;

    float* o0 = g_Wh + ((size_t)h * N_NODES + row0) * OUT_F + c2;
    float* o1 = g_Wh + ((size_t)h * N_NODES + row1) * OUT_F + c2;
#pragma unroll
    for (int j = 0; j < 8; j++) {
        *(float2*)(o0 + j * 8) = make_float2(acc[j][0], acc[j][1]);
        *(float2*)(o1 + j * 8) = make_float2(acc[j][2], acc[j][3]);
    }

    __half* T = (__half*)(sm + WH_T);
    float* av = (float*)(sm + WH_AV);
    if (t < 64) {
        av[t] = a1v[h * OUT_F + t];
        av[64 + t] = a2v[h * OUT_F + t];
    }
    const int ml0 = 16 * wid + g;
#pragma unroll
    for (int j = 0; j < 8; j++) {
        int o = c2 + j * 8;
        T[o * 136 + ml0] = __float2half(acc[j][0]);
        T[(o + 1) * 136 + ml0] = __float2half(acc[j][1]);
        T[o * 136 + ml0 + 8] = __float2half(acc[j][2]);
        T[(o + 1) * 136 + ml0 + 8] = __float2half(acc[j][3]);
    }
    __syncthreads();

#pragma unroll
    for (int i = 0; i < 4; i++) {
        int idx = t * 4 + i;
        int o = idx >> 4, q = idx & 15;
        uint4 v = *(const uint4*)(T + o * 136 + q * 8);
        *(uint4*)(g_WhT_h16 + ((size_t)h * OUT_F + o) * N_NODES + nbase + q * 8) = v;
    }

    float f10 = 0.f, f20 = 0.f, f11 = 0.f, f21 = 0.f;
#pragma unroll
    for (int j = 0; j < 8; j++) {
        int o = c2 + j * 8;
        float a1x = av[o], a1y = av[o + 1];
        float a2x = av[64 + o], a2y = av[64 + o + 1];
        f10 += acc[j][0] * a1x + acc[j][1] * a1y;
        f20 += acc[j][0] * a2x + acc[j][1] * a2y;
        f11 += acc[j][2] * a1x + acc[j][3] * a1y;
        f21 += acc[j][2] * a2x + acc[j][3] * a2y;
    }
#pragma unroll
    for (int off = 1; off <= 2; off <<= 1) {
        f10 += __shfl_xor_sync(0xffffffffu, f10, off);
        f20 += __shfl_xor_sync(0xffffffffu, f20, off);
        f11 += __shfl_xor_sync(0xffffffffu, f11, off);
        f21 += __shfl_xor_sync(0xffffffffu, f21, off);
    }
    if ((lane & 3) == 0) {
        int i0 = h * N_NODES + row0;
        int i1 = h * N_NODES + row1;
        g_f1[i0] = f10;
        g_f2[i0] = f20;
        g_P2[i0] = expf(f20);
        g_Q2[i0] = expf(ALPHA * f20);
        g_f1[i1] = f11;
        g_f2[i1] = f21;
        g_P2[i1] = expf(f21);
        g_Q2[i1] = expf(ALPHA * f21);
    }
}

// ---------------- kernel: per-head max of f2 ----------------
__global__ __launch_bounds__(256) void maxf2_kernel() {
    __shared__ float red[256];
    const int h = blockIdx.x, t = threadIdx.x;
    float m = -3.4e38f;
#pragma unroll
    for (int i = 0; i < 16; i++) m = fmaxf(m, g_f2[h * N_NODES + t + i * 256]);
    red[t] = m;
    __syncthreads();
    for (int s = 128; s; s >>= 1) {
        if (t < s) red[t] = fmaxf(red[t], red[t + s]);
        __syncthreads();
    }
    if (t == 0) g_mx[h] = red[0];
}

// ---------------- kernel: shifted P1/Q1 ----------------
__global__ __launch_bounds__(256) void exp1_kernel() {
    int idx = blockIdx.x * blockDim.x + threadIdx.x;
    int h = idx >> 12;
    float f1 = g_f1[idx];
    float s = f1 + g_mx[h];
    float M = s > 0.f ? s : ALPHA * s;
    g_P1[idx] = expf(f1 - M);
    g_Q1[idx] = expf(ALPHA * f1 - M);
}

// ---------------- kernel: fp16 HMMA fused masked-softmax aggregation ----------------
// 128 rows x 64 cols per CTA, 512 threads / 16 warps, warp tile 16x32, KC2=128.
__global__ __launch_bounds__(512, 2) void gat_mma_kernel(float* __restrict__ out) {
    extern __shared__ __align__(16) char sm[];
    const int t = threadIdx.x;
    const int wid = t >> 5, lane = t & 31;
    const int h = blockIdx.y;
    const int nbase = blockIdx.x * GAT_RT;
    const int hN = h * N_NODES;
    const uint32_t smb = smem_u32(sm);

    // w-gen assignment: row rr (0..127), quarter q -> 32 m's
    const int rr = t >> 2;
    const int q = t & 3;
    const int grow = nbase + rr;
    const float F1r = g_f1[hN + grow];
    const float P1r = g_P1[hN + grow];
    const float Q1r = g_Q1[hN + grow];
    const unsigned* adjrow = g_adjbits + (size_t)grow * (N_NODES / 32);
    float Dacc = 0.f;

    const __half* whTh = g_WhT_h16 + ((size_t)h * OUT_F) * N_NODES;

    // B staging: 1024 quads ([64 o][16 quads]), 2 per thread
    const __half* b_src[2];
    uint32_t b_doff[2];
#pragma unroll
    for (int i = 0; i < 2; i++) {
        int idx = t * 2 + i;
        int br = idx >> 4, bq = idx & 15;
        b_src[i] = whTh + (size_t)br * N_NODES + bq * 8;
        b_doff[i] = (uint32_t)(br * (AST2 * 2) + bq * 16);
    }

    // table staging: chunk cn -> GA_T(cn % 3); 96 quads, threads 0..95
    auto stageT = [&](int cn) {
        if (t < 96) {
            int tb = cn % 3;
            int table = t >> 5, q4 = t & 31;
            const float* base = (table == 0) ? g_f2 : ((table == 1) ? g_P2 : g_Q2);
            cp16(smb + GA_T(tb) + table * 512 + q4 * 16, base + hN + cn * KC2 + q4 * 4);
        }
    };

    // w-gen from SMEM tables -> A buffer `buf` (32 fp16 weights per thread)
    auto wgen = [&](int buf, int tb, unsigned aw) {
        const float* Tf = (const float*)(sm + GA_T(tb));
        const uint32_t dst = smb + GA_A(buf) + rr * (AST2 * 2) + q * 64;
#pragma unroll
        for (int g8 = 0; g8 < 4; g8++) {
            float fv[8], pv[8], qv[8];
            *(float4*)&fv[0] = *(const float4*)&Tf[q * 32 + g8 * 8];
            *(float4*)&fv[4] = *(const float4*)&Tf[q * 32 + g8 * 8 + 4];
            *(float4*)&pv[0] = *(const float4*)&Tf[128 + q * 32 + g8 * 8];
            *(float4*)&pv[4] = *(const float4*)&Tf[128 + q * 32 + g8 * 8 + 4];
            *(float4*)&qv[0] = *(const float4*)&Tf[256 + q * 32 + g8 * 8];
            *(float4*)&qv[4] = *(const float4*)&Tf[256 + q * 32 + g8 * 8 + 4];
            float wv[8];
            float ds = 0.f;
#pragma unroll
            for (int e = 0; e < 8; e++) {
                int bit = g8 * 8 + e;
                float pos = F1r + fv[e];
                float w = (pos > 0.f) ? (P1r * pv[e]) : (Q1r * qv[e]);
                w = ((aw >> bit) & 1u) ? w : 0.f;
                ds += w;
                wv[e] = w;
            }
            Dacc += ds;
            unsigned hp[4];
#pragma unroll
            for (int e = 0; e < 4; e++) {
                __half2 h2 = __floats2half2_rn(wv[2 * e], wv[2 * e + 1]);
                hp[e] = *reinterpret_cast<unsigned*>(&h2);
            }
            asm volatile("st.shared.v4.b32 [%0], {%1, %2, %3, %4};"
                         :: "r"(dst + g8 * 16), "r"(hp[0]), "r"(hp[1]), "r"(hp[2]),
                            "r"(hp[3]) : "memory");
        }
    };

    // ---- prologue: B(0), T(0), T(1); then wgen(0) ----
#pragma unroll
    for (int i = 0; i < 2; i++) cp16(smb + GA_B(0) + b_doff[i], b_src[i]);
    stageT(0);
    stageT(1);
    cp_commit();
    cp_wait<0>();
    __syncthreads();
    wgen(0, 0, adjrow[q]);

    float acc[4][4];
#pragma unroll
    for (int j = 0; j < 4; j++)
#pragma unroll
        for (int e = 0; e < 4; e++) acc[j][e] = 0.f;

    const int rgrp = wid & 7;        // 16-row group
    const int chalf = wid >> 3;      // 32-col half
    const uint32_t aRow = (16 * rgrp + (lane & 15)) * (AST2 * 2) + (lane >> 4) * 16;
    const int jbase = chalf * 32;
    const uint32_t bOff = (jbase + (lane & 7)) * (AST2 * 2) + (lane >> 3) * 16;

    for (int c = 0; c < NCH2; c++) {
        const int p = c & 1, pn = p ^ 1;
        cp_wait<0>();
        __syncthreads();

        unsigned aw_next = 0;
        if (c + 1 < NCH2) {
            aw_next = adjrow[(c + 1) * 4 + q];
#pragma unroll
            for (int i = 0; i < 2; i++)
                cp16(smb + GA_B(pn) + b_doff[i], b_src[i] + (c + 1) * KC2);
            if (c + 2 < NCH2) stageT(c + 2);
            cp_commit();
        }

        // ---- k half 0 (m 0..63 of chunk) ----
        {
            uint32_t af[4][4];
#pragma unroll
            for (int s = 0; s < 4; s++) ldm4(af[s], smb + GA_A(p) + aRow + s * 32);
#pragma unroll
            for (int j = 0; j < 4; j++) {
                uint32_t b0[4], b1[4];
                const uint32_t bj = smb + GA_B(p) + j * 8 * (AST2 * 2) + bOff;
                ldm4(b0, bj);
                ldm4(b1, bj + 64);
                mma_f16(acc[j], af[0], b0[0], b0[1]);
                mma_f16(acc[j], af[1], b0[2], b0[3]);
                mma_f16(acc[j], af[2], b1[0], b1[1]);
                mma_f16(acc[j], af[3], b1[2], b1[3]);
            }
        }

        // w-gen for next chunk (overlaps tensor work of half 0)
        if (c + 1 < NCH2) wgen(pn, (c + 1) % 3, aw_next);

        // ---- k half 1 (m 64..127 of chunk) ----
        {
            uint32_t af[4][4];
#pragma unroll
            for (int s = 0; s < 4; s++) ldm4(af[s], smb + GA_A(p) + aRow + 128 + s * 32);
#pragma unroll
            for (int j = 0; j < 4; j++) {
                uint32_t b0[4], b1[4];
                const uint32_t bj = smb + GA_B(p) + j * 8 * (AST2 * 2) + bOff + 128;
                ldm4(b0, bj);
                ldm4(b1, bj + 64);
                mma_f16(acc[j], af[0], b0[0], b0[1]);
                mma_f16(acc[j], af[1], b0[2], b0[3]);
                mma_f16(acc[j], af[2], b1[0], b1[1]);
                mma_f16(acc[j], af[3], b1[2], b1[3]);
            }
        }
    }

    float* Dsh = (float*)(sm + GA_DSH);
    Dsh[t] = Dacc;
    __syncthreads();

    const int g = lane >> 2;
    const int row0 = 16 * rgrp + g;
    const int row1 = row0 + 8;
    const float inv0 =
        1.0f / (Dsh[4 * row0] + Dsh[4 * row0 + 1] + Dsh[4 * row0 + 2] + Dsh[4 * row0 + 3]);
    const float inv1 =
        1.0f / (Dsh[4 * row1] + Dsh[4 * row1 + 1] + Dsh[4 * row1 + 2] + Dsh[4 * row1 + 3]);
    float* o0 = out + (size_t)(nbase + row0) * (HEADS * OUT_F) + h * OUT_F + jbase +
                (lane & 3) * 2;
    float* o1 = out + (size_t)(nbase + row1) * (HEADS * OUT_F) + h * OUT_F + jbase +
                (lane & 3) * 2;
#pragma unroll
    for (int j = 0; j < 4; j++) {
        *(float2*)(o0 + j * 8) = make_float2(acc[j][0] * inv0, acc[j][1] * inv0);
        *(float2*)(o1 + j * 8) = make_float2(acc[j][2] * inv1, acc[j][3] * inv1);
    }
}

// ---------------- launch ----------------
extern "C" void kernel_launch(void* const* d_in, const int* in_sizes, int n_in,
                              void* d_out, int out_size) {
    const float* x   = (const float*)d_in[0];
    const int*   adj = (const int*)d_in[1];
    const float* W   = (const float*)d_in[2];
    const float* a1  = (const float*)d_in[3];
    const float* a2  = (const float*)d_in[4];
    float* out = (float*)d_out;

    cudaFuncSetAttribute(wh_mma_kernel, cudaFuncAttributeMaxDynamicSharedMemorySize,
                         WH_SMEM);
    cudaFuncSetAttribute(gat_mma_kernel, cudaFuncAttributeMaxDynamicSharedMemorySize,
                         GA_SMEM);

    prep_kernel<<<3080, 256>>>(adj, x, W);

    dim3 gW(N_NODES / RT, HEADS);
    wh_mma_kernel<<<gW, 256, WH_SMEM>>>(a1, a2);

    maxf2_kernel<<<HEADS, 256>>>();
    exp1_kernel<<<(HEADS * N_NODES) / 256, 256>>>();

    dim3 gD(N_NODES / GAT_RT, HEADS);
    gat_mma_kernel<<<gD, 512, GA_SMEM>>>(out);
}

// round 14
// speedup vs baseline: 1.3966x; 1.3966x over previous
#include <cuda_runtime.h>
#include <cuda_bf16.h>
#include <cuda_fp16.h>
#include <cstdint>

#define N_NODES 4096
#define IN_F 512
#define OUT_F 64
#define HEADS 8
#define ALPHA 0.2f

#define RT 128                 // rows per CTA (wh kernel)
#define KC 32                  // k per chunk (wh kernel)
#define NCH_W (IN_F / KC)      // 16 chunks (wh)
#define ASTR 40                // padded bf16 row stride (80 B) (wh kernel)
#define BSTR 40

// ---- wh dynamic smem offsets ----
#define WH_A(buf, prec) ((buf) * 20480 + (prec) * 10240)
#define WH_B(buf, prec) (40960 + (buf) * 10240 + (prec) * 5120)
#define WH_T 0                  // epilogue transpose tile [64][136] fp16 (17408 B)
#define WH_AV 18432             // epilogue a1/a2 staging (128 floats)
#define WH_SMEM 61440

// ---- gat (fp16, 128x64 tile, 512 threads, KC2=64, smem tables) ----
#define GAT_RT 128
#define KC2 64
#define NCH2 (N_NODES / KC2)   // 64 chunks
#define AST2 72                // fp16 stride (144 B)
#define GA_A(buf) ((buf) * 18432)           // [128][72] fp16, 2 bufs
#define GA_B(buf) (36864 + (buf) * 9216)    // [64][72] fp16, 2 bufs
#define GA_T(tb)  (55296 + (tb) * 768)      // [3 tables][64] float, 3 bufs
#define GA_DSH 57600                        // 512 floats
#define GA_SMEM 59904

// ---------------- scratch (device globals; no allocation) ----------------
__device__ __align__(16) float g_Wh[HEADS * N_NODES * OUT_F];          // 8 MB [h][n][o]
__device__ float g_f1[HEADS * N_NODES];
__device__ float g_f2[HEADS * N_NODES];
__device__ float g_P2[HEADS * N_NODES];   // exp(f2)
__device__ float g_Q2[HEADS * N_NODES];   // exp(a*f2)
__device__ float g_mx[HEADS];             // per-head max f2
__device__ unsigned g_adjbits[N_NODES * (N_NODES / 32)];               // 2 MB
__device__ __align__(16) __half g_WhT_h16[HEADS * OUT_F * N_NODES];    // 4 MB [h][o][m]
__device__ __align__(16) __nv_bfloat16 g_x_hi[N_NODES * IN_F];         // 4 MB [n][k]
__device__ __align__(16) __nv_bfloat16 g_x_lo[N_NODES * IN_F];
__device__ __align__(16) __nv_bfloat16 g_WT_hi[HEADS * OUT_F * IN_F];  // 512 KB [h][o][k]
__device__ __align__(16) __nv_bfloat16 g_WT_lo[HEADS * OUT_F * IN_F];

// ---------------- helpers ----------------
__device__ __forceinline__ uint32_t smem_u32(const void* p) {
    uint32_t a;
    asm("{ .reg .u64 t; cvta.to.shared.u64 t, %1; cvt.u32.u64 %0, t; }" : "=r"(a) : "l"(p));
    return a;
}
__device__ __forceinline__ void cp16(uint32_t dst, const void* src) {
    asm volatile("cp.async.cg.shared.global [%0], [%1], 16;" :: "r"(dst), "l"(src) : "memory");
}
__device__ __forceinline__ void cp_commit() {
    asm volatile("cp.async.commit_group;" ::: "memory");
}
template <int N>
__device__ __forceinline__ void cp_wait() {
    asm volatile("cp.async.wait_group %0;" :: "n"(N) : "memory");
}
__device__ __forceinline__ void ldm4(uint32_t* r, uint32_t addr) {
    asm volatile("ldmatrix.sync.aligned.m8n8.x4.shared.b16 {%0,%1,%2,%3}, [%4];"
                 : "=r"(r[0]), "=r"(r[1]), "=r"(r[2]), "=r"(r[3]) : "r"(addr) : "memory");
}
__device__ __forceinline__ void mma_bf16(float* c, const uint32_t* a, uint32_t b0,
                                         uint32_t b1) {
    asm("mma.sync.aligned.m16n8k16.row.col.f32.bf16.bf16.f32 "
        "{%0,%1,%2,%3}, {%4,%5,%6,%7}, {%8,%9}, {%0,%1,%2,%3};"
        : "+f"(c[0]), "+f"(c[1]), "+f"(c[2]), "+f"(c[3])
        : "r"(a[0]), "r"(a[1]), "r"(a[2]), "r"(a[3]), "r"(b0), "r"(b1));
}
__device__ __forceinline__ void mma_f16(float* c, const uint32_t* a, uint32_t b0,
                                        uint32_t b1) {
    asm("mma.sync.aligned.m16n8k16.row.col.f32.f16.f16.f32 "
        "{%0,%1,%2,%3}, {%4,%5,%6,%7}, {%8,%9}, {%0,%1,%2,%3};"
        : "+f"(c[0]), "+f"(c[1]), "+f"(c[2]), "+f"(c[3])
        : "r"(a[0]), "r"(a[1]), "r"(a[2]), "r"(a[3]), "r"(b0), "r"(b1));
}
__device__ __forceinline__ void split_pair(float x, float y, unsigned& hi, unsigned& lo) {
    __nv_bfloat162 h2 = __float22bfloat162_rn(make_float2(x, y));
    float2 hf = __bfloat1622float2(h2);
    __nv_bfloat162 l2 = __float22bfloat162_rn(make_float2(x - hf.x, y - hf.y));
    hi = *reinterpret_cast<unsigned*>(&h2);
    lo = *reinterpret_cast<unsigned*>(&l2);
}

// ---------------- kernel: fused prep (bitpack | xsplit | wsplit) ----------------
__global__ __launch_bounds__(256) void prep_kernel(const int* __restrict__ adj,
                                                   const float* __restrict__ x,
                                                   const float* __restrict__ W) {
    const int b = blockIdx.x;
    const int tid = threadIdx.x;
    if (b < 2048) {
        // bitpack: 32 adj entries per thread
        int t = b * 256 + tid;
        const int4* p = (const int4*)adj + (size_t)t * 8;
        unsigned w = 0;
#pragma unroll
        for (int i = 0; i < 8; i++) {
            int4 v = p[i];
            w |= (v.x > 0 ? 1u : 0u) << (4 * i);
            w |= (v.y > 0 ? 1u : 0u) << (4 * i + 1);
            w |= (v.z > 0 ? 1u : 0u) << (4 * i + 2);
            w |= (v.w > 0 ? 1u : 0u) << (4 * i + 3);
        }
        g_adjbits[t] = w;
    } else if (b < 3072) {
        // xsplit: 8 floats per thread
        int gid = (b - 2048) * 256 + tid;
        const float4* xp = (const float4*)x + gid * 2;
        float4 v0 = xp[0], v1 = xp[1];
        float f[8] = {v0.x, v0.y, v0.z, v0.w, v1.x, v1.y, v1.z, v1.w};
        unsigned hw[4], lw[4];
#pragma unroll
        for (int i = 0; i < 4; i++) split_pair(f[2 * i], f[2 * i + 1], hw[i], lw[i]);
        *(uint4*)(g_x_hi + (size_t)gid * 8) = make_uint4(hw[0], hw[1], hw[2], hw[3]);
        *(uint4*)(g_x_lo + (size_t)gid * 8) = make_uint4(lw[0], lw[1], lw[2], lw[3]);
    } else {
        // wsplit: one head per block
        const int h = b - 3072;
#pragma unroll 4
        for (int i = 0; i < 128; i++) {
            int lin = i * 256 + tid;
            int o = lin >> 9, k = lin & 511;
            float v = W[((size_t)h * IN_F + k) * OUT_F + o];
            __nv_bfloat16 hb = __float2bfloat16(v);
            __nv_bfloat16 lb = __float2bfloat16(v - __bfloat162float(hb));
            size_t d = ((size_t)h * OUT_F + o) * IN_F + k;
            g_WT_hi[d] = hb;
            g_WT_lo[d] = lb;
        }
    }
}

// ---------------- kernel: Wh = x @ W via HMMA + fused f1/f2/exp/WhT epilogue ----------------
__global__ __launch_bounds__(256, 2) void wh_mma_kernel(const float* __restrict__ a1v,
                                                        const float* __restrict__ a2v) {
    extern __shared__ __align__(16) char sm[];
    const int t = threadIdx.x;
    const int wid = t >> 5, lane = t & 31;
    const int h = blockIdx.y;
    const int nbase = blockIdx.x * RT;

    const int a_p[4] = {(t * 4) >> 9, (t * 4 + 1) >> 9, (t * 4 + 2) >> 9, (t * 4 + 3) >> 9};
    int a_r[4], a_q[4];
    const __nv_bfloat16* a_src[4];
    uint32_t a_doff[4];
#pragma unroll
    for (int i = 0; i < 4; i++) {
        int idx = t * 4 + i;
        a_r[i] = (idx >> 2) & 127;
        a_q[i] = idx & 3;
        a_src[i] = (a_p[i] ? g_x_lo : g_x_hi) + (size_t)(nbase + a_r[i]) * IN_F + a_q[i] * 8;
        a_doff[i] = (uint32_t)(a_r[i] * (ASTR * 2) + a_q[i] * 16);
    }
    int b_p[2];
    const __nv_bfloat16* b_src[2];
    uint32_t b_doff[2];
#pragma unroll
    for (int i = 0; i < 2; i++) {
        int idx = t * 2 + i;
        b_p[i] = idx >> 8;
        int br = (idx >> 2) & 63, bq = idx & 3;
        b_src[i] = (b_p[i] ? g_WT_lo : g_WT_hi) + ((size_t)h * OUT_F + br) * IN_F + bq * 8;
        b_doff[i] = (uint32_t)(br * (BSTR * 2) + bq * 16);
    }
    const uint32_t smb = smem_u32(sm);

#pragma unroll
    for (int i = 0; i < 4; i++) cp16(smb + WH_A(0, a_p[i]) + a_doff[i], a_src[i]);
#pragma unroll
    for (int i = 0; i < 2; i++) cp16(smb + WH_B(0, b_p[i]) + b_doff[i], b_src[i]);
    cp_commit();

    float acc[8][4];
#pragma unroll
    for (int j = 0; j < 8; j++)
#pragma unroll
        for (int q = 0; q < 4; q++) acc[j][q] = 0.f;

    const uint32_t aRow = (16 * wid + (lane & 15)) * (ASTR * 2) + (lane >> 4) * 16;
    const uint32_t bRow = (lane & 7) * (BSTR * 2) + (lane >> 3) * 16;

    for (int c = 0; c < NCH_W; c++) {
        const int p = c & 1, pn = p ^ 1;
        cp_wait<0>();
        __syncthreads();
        if (c + 1 < NCH_W) {
            const int kb = (c + 1) * KC;
#pragma unroll
            for (int i = 0; i < 4; i++) cp16(smb + WH_A(pn, a_p[i]) + a_doff[i], a_src[i] + kb);
#pragma unroll
            for (int i = 0; i < 2; i++) cp16(smb + WH_B(pn, b_p[i]) + b_doff[i], b_src[i] + kb);
            cp_commit();
        }
        uint32_t afh[2][4], afl[2][4];
        ldm4(afh[0], smb + WH_A(p, 0) + aRow);
        ldm4(afh[1], smb + WH_A(p, 0) + aRow + 32);
        ldm4(afl[0], smb + WH_A(p, 1) + aRow);
        ldm4(afl[1], smb + WH_A(p, 1) + aRow + 32);
#pragma unroll
        for (int j = 0; j < 8; j++) {
            uint32_t bh[4], bl[4];
            ldm4(bh, smb + WH_B(p, 0) + j * 8 * (BSTR * 2) + bRow);
            ldm4(bl, smb + WH_B(p, 1) + j * 8 * (BSTR * 2) + bRow);
            mma_bf16(acc[j], afh[0], bh[0], bh[1]);
            mma_bf16(acc[j], afh[0], bl[0], bl[1]);
            mma_bf16(acc[j], afl[0], bh[0], bh[1]);
            mma_bf16(acc[j], afh[1], bh[2], bh[3]);
            mma_bf16(acc[j], afh[1], bl[2], bl[3]);
            mma_bf16(acc[j], afl[1], bh[2], bh[3]);
        }
        __syncthreads();
    }

    // ---------- fused epilogue ----------
    const int g = lane >> 2;
    const int c2 = (lane & 3) * 2;          // column pair base
    const int row0 = nbase + 16 * wid + g;  // global row for acc[.][0..1]
    const int row1 = row0 + 8;              // global row for acc[.][2..3]

    // 1) write fp32 Wh
    float* o0 = g_Wh + ((size_t)h * N_NODES + row0) * OUT_F + c2;
    float* o1 = g_Wh + ((size_t)h * N_NODES + row1) * OUT_F + c2;
#pragma unroll
    for (int j = 0; j < 8; j++) {
        *(float2*)(o0 + j * 8) = make_float2(acc[j][0], acc[j][1]);
        *(float2*)(o1 + j * 8) = make_float2(acc[j][2], acc[j][3]);
    }

    // 2) stage transpose tile + a1/a2 vectors
    __half* T = (__half*)(sm + WH_T);       // [64][136] fp16
    float* av = (float*)(sm + WH_AV);       // a1[64], a2[64]
    if (t < 64) {
        av[t] = a1v[h * OUT_F + t];
        av[64 + t] = a2v[h * OUT_F + t];
    }
    const int ml0 = 16 * wid + g;           // CTA-local m for row0
#pragma unroll
    for (int j = 0; j < 8; j++) {
        int o = c2 + j * 8;
        T[o * 136 + ml0] = __float2half(acc[j][0]);
        T[(o + 1) * 136 + ml0] = __float2half(acc[j][1]);
        T[o * 136 + ml0 + 8] = __float2half(acc[j][2]);
        T[(o + 1) * 136 + ml0 + 8] = __float2half(acc[j][3]);
    }
    __syncthreads();

    // 3) write WhT fp16 (coalesced uint4)
#pragma unroll
    for (int i = 0; i < 4; i++) {
        int idx = t * 4 + i;                // 1024 uint4
        int o = idx >> 4, q = idx & 15;
        uint4 v = *(const uint4*)(T + o * 136 + q * 8);
        *(uint4*)(g_WhT_h16 + ((size_t)h * OUT_F + o) * N_NODES + nbase + q * 8) = v;
    }

    // 4) f1/f2 dots + exp tables
    float f10 = 0.f, f20 = 0.f, f11 = 0.f, f21 = 0.f;
#pragma unroll
    for (int j = 0; j < 8; j++) {
        int o = c2 + j * 8;
        float a1x = av[o], a1y = av[o + 1];
        float a2x = av[64 + o], a2y = av[64 + o + 1];
        f10 += acc[j][0] * a1x + acc[j][1] * a1y;
        f20 += acc[j][0] * a2x + acc[j][1] * a2y;
        f11 += acc[j][2] * a1x + acc[j][3] * a1y;
        f21 += acc[j][2] * a2x + acc[j][3] * a2y;
    }
#pragma unroll
    for (int off = 1; off <= 2; off <<= 1) {
        f10 += __shfl_xor_sync(0xffffffffu, f10, off);
        f20 += __shfl_xor_sync(0xffffffffu, f20, off);
        f11 += __shfl_xor_sync(0xffffffffu, f11, off);
        f21 += __shfl_xor_sync(0xffffffffu, f21, off);
    }
    if ((lane & 3) == 0) {
        int i0 = h * N_NODES + row0;
        int i1 = h * N_NODES + row1;
        g_f1[i0] = f10;
        g_f2[i0] = f20;
        g_P2[i0] = expf(f20);
        g_Q2[i0] = expf(ALPHA * f20);
        g_f1[i1] = f11;
        g_f2[i1] = f21;
        g_P2[i1] = expf(f21);
        g_Q2[i1] = expf(ALPHA * f21);
    }
}

// ---------------- kernel: per-head max of f2 ----------------
__global__ __launch_bounds__(256) void maxf2_kernel() {
    __shared__ float red[256];
    const int h = blockIdx.x, t = threadIdx.x;
    float m = -3.4e38f;
#pragma unroll
    for (int i = 0; i < 16; i++) m = fmaxf(m, g_f2[h * N_NODES + t + i * 256]);
    red[t] = m;
    __syncthreads();
    for (int s = 128; s; s >>= 1) {
        if (t < s) red[t] = fmaxf(red[t], red[t + s]);
        __syncthreads();
    }
    if (t == 0) g_mx[h] = red[0];
}

// ---------------- kernel: fp16 HMMA fused masked-softmax aggregation ----------------
// 128 rows x 64 cols per CTA, 512 threads / 16 warps, warp tile 16x32.
// P1/Q1 computed in-prologue from f1 + per-head max (exp1 kernel folded in).
__global__ __launch_bounds__(512, 2) void gat_mma_kernel(float* __restrict__ out) {
    extern __shared__ __align__(16) char sm[];
    const int t = threadIdx.x;
    const int wid = t >> 5, lane = t & 31;
    const int h = blockIdx.y;
    const int nbase = blockIdx.x * GAT_RT;
    const int hN = h * N_NODES;
    const uint32_t smb = smem_u32(sm);

    // w-gen assignment: row rr (0..127), quarter q -> 16 m's
    const int rr = t >> 2;
    const int q = t & 3;
    const int grow = nbase + rr;
    const float F1r = g_f1[hN + grow];
    // fold exp1: M = leakyrelu(f1 + max f2); P1 = exp(f1-M), Q1 = exp(a*f1-M)
    const float sM = F1r + g_mx[h];
    const float Mr = sM > 0.f ? sM : ALPHA * sM;
    const float P1r = expf(F1r - Mr);
    const float Q1r = expf(ALPHA * F1r - Mr);
    const unsigned* adjrow = g_adjbits + (size_t)grow * (N_NODES / 32);
    float Dacc = 0.f;

    const __half* whTh = g_WhT_h16 + ((size_t)h * OUT_F) * N_NODES;

    // B staging: 512 quads ([64 o][8 quads]), 1 per thread
    const int br = t >> 3, bq = t & 7;
    const __half* b_src = whTh + (size_t)br * N_NODES + bq * 8;
    const uint32_t b_doff = (uint32_t)(br * (AST2 * 2) + bq * 16);

    auto stageT = [&](int cn) {
        if (t < 48) {
            int tb = cn % 3;
            int table = t >> 4, q4 = t & 15;
            const float* base = (table == 0) ? g_f2 : ((table == 1) ? g_P2 : g_Q2);
            cp16(smb + GA_T(tb) + table * 256 + q4 * 16, base + hN + cn * KC2 + q4 * 4);
        }
    };

    auto wgen = [&](int buf, int tb, unsigned awfull) {
        const float* Tf = (const float*)(sm + GA_T(tb));
        const unsigned aw = awfull >> ((q & 1) * 16);
        const uint32_t dst = smb + GA_A(buf) + rr * (AST2 * 2) + q * 32;
#pragma unroll
        for (int g4 = 0; g4 < 2; g4++) {
            float fv[8], pv[8], qv[8];
            *(float4*)&fv[0] = *(const float4*)&Tf[q * 16 + g4 * 8];
            *(float4*)&fv[4] = *(const float4*)&Tf[q * 16 + g4 * 8 + 4];
            *(float4*)&pv[0] = *(const float4*)&Tf[64 + q * 16 + g4 * 8];
            *(float4*)&pv[4] = *(const float4*)&Tf[64 + q * 16 + g4 * 8 + 4];
            *(float4*)&qv[0] = *(const float4*)&Tf[128 + q * 16 + g4 * 8];
            *(float4*)&qv[4] = *(const float4*)&Tf[128 + q * 16 + g4 * 8 + 4];
            float wv[8];
            float ds = 0.f;
#pragma unroll
            for (int e = 0; e < 8; e++) {
                int bit = g4 * 8 + e;
                float pos = F1r + fv[e];
                float w = (pos > 0.f) ? (P1r * pv[e]) : (Q1r * qv[e]);
                w = ((aw >> bit) & 1u) ? w : 0.f;
                ds += w;
                wv[e] = w;
            }
            Dacc += ds;
            unsigned hp[4];
#pragma unroll
            for (int e = 0; e < 4; e++) {
                __half2 h2 = __floats2half2_rn(wv[2 * e], wv[2 * e + 1]);
                hp[e] = *reinterpret_cast<unsigned*>(&h2);
            }
            asm volatile("st.shared.v4.b32 [%0], {%1, %2, %3, %4};"
                         :: "r"(dst + g4 * 16), "r"(hp[0]), "r"(hp[1]), "r"(hp[2]),
                            "r"(hp[3]) : "memory");
        }
    };

    // ---- prologue: B(0), T(0), T(1); then wgen(0) ----
    cp16(smb + GA_B(0) + b_doff, b_src);
    stageT(0);
    stageT(1);
    cp_commit();
    cp_wait<0>();
    __syncthreads();
    {
        unsigned aw0 = adjrow[q >> 1];
        wgen(0, 0, aw0);
    }

    float acc[4][4];
#pragma unroll
    for (int j = 0; j < 4; j++)
#pragma unroll
        for (int e = 0; e < 4; e++) acc[j][e] = 0.f;

    const int rgrp = wid & 7;        // 16-row group
    const int chalf = wid >> 3;      // 32-col half
    const uint32_t aRow = (16 * rgrp + (lane & 15)) * (AST2 * 2) + (lane >> 4) * 16;
    const int jbase = chalf * 32;    // output-column base
    const uint32_t bOff = (jbase + (lane & 7)) * (AST2 * 2) + (lane >> 3) * 16;

    for (int c = 0; c < NCH2; c++) {
        const int p = c & 1, pn = p ^ 1;
        cp_wait<0>();
        __syncthreads();

        unsigned aw_next = 0;
        if (c + 1 < NCH2) {
            aw_next = adjrow[(c + 1) * 2 + (q >> 1)];
            cp16(smb + GA_B(pn) + b_doff, b_src + (c + 1) * KC2);
            if (c + 2 < NCH2) stageT(c + 2);
            cp_commit();
        }

        uint32_t af[4][4];
#pragma unroll
        for (int s = 0; s < 4; s++) ldm4(af[s], smb + GA_A(p) + aRow + s * 32);
#pragma unroll
        for (int j = 0; j < 4; j++) {
            uint32_t b0[4], b1[4];
            const uint32_t bj = smb + GA_B(p) + j * 8 * (AST2 * 2) + bOff;
            ldm4(b0, bj);
            ldm4(b1, bj + 64);
            mma_f16(acc[j], af[0], b0[0], b0[1]);
            mma_f16(acc[j], af[1], b0[2], b0[3]);
            mma_f16(acc[j], af[2], b1[0], b1[1]);
            mma_f16(acc[j], af[3], b1[2], b1[3]);
        }

        if (c + 1 < NCH2) wgen(pn, (c + 1) % 3, aw_next);
    }

    float* Dsh = (float*)(sm + GA_DSH);
    Dsh[t] = Dacc;
    __syncthreads();

    const int g = lane >> 2;
    const int row0 = 16 * rgrp + g;
    const int row1 = row0 + 8;
    const float inv0 =
        1.0f / (Dsh[4 * row0] + Dsh[4 * row0 + 1] + Dsh[4 * row0 + 2] + Dsh[4 * row0 + 3]);
    const float inv1 =
        1.0f / (Dsh[4 * row1] + Dsh[4 * row1 + 1] + Dsh[4 * row1 + 2] + Dsh[4 * row1 + 3]);
    float* o0 = out + (size_t)(nbase + row0) * (HEADS * OUT_F) + h * OUT_F + jbase +
                (lane & 3) * 2;
    float* o1 = out + (size_t)(nbase + row1) * (HEADS * OUT_F) + h * OUT_F + jbase +
                (lane & 3) * 2;
#pragma unroll
    for (int j = 0; j < 4; j++) {
        *(float2*)(o0 + j * 8) = make_float2(acc[j][0] * inv0, acc[j][1] * inv0);
        *(float2*)(o1 + j * 8) = make_float2(acc[j][2] * inv1, acc[j][3] * inv1);
    }
}

// ---------------- launch ----------------
extern "C" void kernel_launch(void* const* d_in, const int* in_sizes, int n_in,
                              void* d_out, int out_size) {
    const float* x   = (const float*)d_in[0];
    const int*   adj = (const int*)d_in[1];
    const float* W   = (const float*)d_in[2];
    const float* a1  = (const float*)d_in[3];
    const float* a2  = (const float*)d_in[4];
    float* out = (float*)d_out;

    cudaFuncSetAttribute(wh_mma_kernel, cudaFuncAttributeMaxDynamicSharedMemorySize,
                         WH_SMEM);
    cudaFuncSetAttribute(gat_mma_kernel, cudaFuncAttributeMaxDynamicSharedMemorySize,
                         GA_SMEM);

    prep_kernel<<<3080, 256>>>(adj, x, W);

    dim3 gW(N_NODES / RT, HEADS);
    wh_mma_kernel<<<gW, 256, WH_SMEM>>>(a1, a2);

    maxf2_kernel<<<HEADS, 256>>>();

    dim3 gD(N_NODES / GAT_RT, HEADS);
    gat_mma_kernel<<<gD, 512, GA_SMEM>>>(out);
}

// round 15
// speedup vs baseline: 1.8257x; 1.3073x over previous
#include <cuda_runtime.h>
#include <cuda_bf16.h>
#include <cuda_fp16.h>
#include <cstdint>

#define N_NODES 4096
#define IN_F 512
#define OUT_F 64
#define HEADS 8
#define ALPHA 0.2f

#define RT 128                 // rows per CTA (wh kernel)
#define KC 32                  // k per chunk (wh kernel)
#define NCH_W (IN_F / KC)      // 16 chunks (wh)
#define ASTR 40                // padded bf16 row stride (80 B) (wh kernel)
#define BSTR 40

// ---- wh dynamic smem offsets ----
#define WH_A(buf, prec) ((buf) * 20480 + (prec) * 10240)
#define WH_B(buf, prec) (40960 + (buf) * 10240 + (prec) * 5120)
#define WH_T 0                  // epilogue transpose tile [64][136] fp16 (17408 B)
#define WH_AV 18432             // epilogue a1/a2 staging (128 floats)
#define WH_SMEM 61440

// ---- gat (fp16, 128x64 tile, 512 threads, KC2=64, register-fragment A) ----
#define GAT_RT 128
#define KC2 64
#define NCH2 (N_NODES / KC2)   // 64 chunks
#define AST2 72                // fp16 stride (144 B) for B tile
#define GB_B(buf)  ((buf) * 9216)            // [64][72] fp16, 2 bufs
#define GB_TAB(tb) (18432 + (tb) * 256)      // 32 pairs x {P2h2,Q2h2}, 3 bufs
#define GB_ADJ(buf) (19200 + (buf) * 1024)   // 128 rows x 8 B, 2 bufs
#define GB_SMEM 21504

// ---------------- scratch (device globals; no allocation) ----------------
__device__ __align__(16) float g_Wh[HEADS * N_NODES * OUT_F];          // 8 MB [h][n][o]
__device__ float g_f1[HEADS * N_NODES];
__device__ float g_f2[HEADS * N_NODES];
__device__ float g_P2[HEADS * N_NODES];   // exp(f2)
__device__ float g_Q2[HEADS * N_NODES];   // exp(a*f2)
__device__ float g_mx[HEADS];             // per-head max f2
__device__ __align__(16) uint2 g_tab2[HEADS * (N_NODES / 2)];          // {P2h2,Q2h2}/pair
__device__ __align__(16) unsigned g_adjbits[N_NODES * (N_NODES / 32)]; // 2 MB
__device__ __align__(16) __half g_WhT_h16[HEADS * OUT_F * N_NODES];    // 4 MB [h][o][m]
__device__ __align__(16) __nv_bfloat16 g_x_hi[N_NODES * IN_F];         // 4 MB [n][k]
__device__ __align__(16) __nv_bfloat16 g_x_lo[N_NODES * IN_F];
__device__ __align__(16) __nv_bfloat16 g_WT_hi[HEADS * OUT_F * IN_F];  // 512 KB
__device__ __align__(16) __nv_bfloat16 g_WT_lo[HEADS * OUT_F * IN_F];

// ---------------- helpers ----------------
__device__ __forceinline__ uint32_t smem_u32(const void* p) {
    uint32_t a;
    asm("{ .reg .u64 t; cvta.to.shared.u64 t, %1; cvt.u32.u64 %0, t; }" : "=r"(a) : "l"(p));
    return a;
}
__device__ __forceinline__ void cp16(uint32_t dst, const void* src) {
    asm volatile("cp.async.cg.shared.global [%0], [%1], 16;" :: "r"(dst), "l"(src) : "memory");
}
__device__ __forceinline__ void cp8(uint32_t dst, const void* src) {
    asm volatile("cp.async.ca.shared.global [%0], [%1], 8;" :: "r"(dst), "l"(src) : "memory");
}
__device__ __forceinline__ void cp_commit() {
    asm volatile("cp.async.commit_group;" ::: "memory");
}
template <int N>
__device__ __forceinline__ void cp_wait() {
    asm volatile("cp.async.wait_group %0;" :: "n"(N) : "memory");
}
__device__ __forceinline__ void ldm4(uint32_t* r, uint32_t addr) {
    asm volatile("ldmatrix.sync.aligned.m8n8.x4.shared.b16 {%0,%1,%2,%3}, [%4];"
                 : "=r"(r[0]), "=r"(r[1]), "=r"(r[2]), "=r"(r[3]) : "r"(addr) : "memory");
}
__device__ __forceinline__ void mma_bf16(float* c, const uint32_t* a, uint32_t b0,
                                         uint32_t b1) {
    asm("mma.sync.aligned.m16n8k16.row.col.f32.bf16.bf16.f32 "
        "{%0,%1,%2,%3}, {%4,%5,%6,%7}, {%8,%9}, {%0,%1,%2,%3};"
        : "+f"(c[0]), "+f"(c[1]), "+f"(c[2]), "+f"(c[3])
        : "r"(a[0]), "r"(a[1]), "r"(a[2]), "r"(a[3]), "r"(b0), "r"(b1));
}
__device__ __forceinline__ void mma_f16(float* c, const uint32_t* a, uint32_t b0,
                                        uint32_t b1) {
    asm("mma.sync.aligned.m16n8k16.row.col.f32.f16.f16.f32 "
        "{%0,%1,%2,%3}, {%4,%5,%6,%7}, {%8,%9}, {%0,%1,%2,%3};"
        : "+f"(c[0]), "+f"(c[1]), "+f"(c[2]), "+f"(c[3])
        : "r"(a[0]), "r"(a[1]), "r"(a[2]), "r"(a[3]), "r"(b0), "r"(b1));
}
__device__ __forceinline__ void split_pair(float x, float y, unsigned& hi, unsigned& lo) {
    __nv_bfloat162 h2 = __float22bfloat162_rn(make_float2(x, y));
    float2 hf = __bfloat1622float2(h2);
    __nv_bfloat162 l2 = __float22bfloat162_rn(make_float2(x - hf.x, y - hf.y));
    hi = *reinterpret_cast<unsigned*>(&h2);
    lo = *reinterpret_cast<unsigned*>(&l2);
}
__device__ __forceinline__ unsigned h2bits(__half2 v) {
    return *reinterpret_cast<unsigned*>(&v);
}

// ---------------- kernel: fused prep (bitpack | xsplit | wsplit) ----------------
__global__ __launch_bounds__(256) void prep_kernel(const int* __restrict__ adj,
                                                   const float* __restrict__ x,
                                                   const float* __restrict__ W) {
    const int b = blockIdx.x;
    const int tid = threadIdx.x;
    if (b < 2048) {
        int t = b * 256 + tid;
        const int4* p = (const int4*)adj + (size_t)t * 8;
        unsigned w = 0;
#pragma unroll
        for (int i = 0; i < 8; i++) {
            int4 v = p[i];
            w |= (v.x > 0 ? 1u : 0u) << (4 * i);
            w |= (v.y > 0 ? 1u : 0u) << (4 * i + 1);
            w |= (v.z > 0 ? 1u : 0u) << (4 * i + 2);
            w |= (v.w > 0 ? 1u : 0u) << (4 * i + 3);
        }
        g_adjbits[t] = w;
    } else if (b < 3072) {
        int gid = (b - 2048) * 256 + tid;
        const float4* xp = (const float4*)x + gid * 2;
        float4 v0 = xp[0], v1 = xp[1];
        float f[8] = {v0.x, v0.y, v0.z, v0.w, v1.x, v1.y, v1.z, v1.w};
        unsigned hw[4], lw[4];
#pragma unroll
        for (int i = 0; i < 4; i++) split_pair(f[2 * i], f[2 * i + 1], hw[i], lw[i]);
        *(uint4*)(g_x_hi + (size_t)gid * 8) = make_uint4(hw[0], hw[1], hw[2], hw[3]);
        *(uint4*)(g_x_lo + (size_t)gid * 8) = make_uint4(lw[0], lw[1], lw[2], lw[3]);
    } else {
        const int h = b - 3072;
#pragma unroll 4
        for (int i = 0; i < 128; i++) {
            int lin = i * 256 + tid;
            int o = lin >> 9, k = lin & 511;
            float v = W[((size_t)h * IN_F + k) * OUT_F + o];
            __nv_bfloat16 hb = __float2bfloat16(v);
            __nv_bfloat16 lb = __float2bfloat16(v - __bfloat162float(hb));
            size_t d = ((size_t)h * OUT_F + o) * IN_F + k;
            g_WT_hi[d] = hb;
            g_WT_lo[d] = lb;
        }
    }
}

// ---------------- kernel: Wh = x @ W via HMMA + fused f1/f2/exp/WhT epilogue ----------------
__global__ __launch_bounds__(256, 2) void wh_mma_kernel(const float* __restrict__ a1v,
                                                        const float* __restrict__ a2v) {
    extern __shared__ __align__(16) char sm[];
    const int t = threadIdx.x;
    const int wid = t >> 5, lane = t & 31;
    const int h = blockIdx.y;
    const int nbase = blockIdx.x * RT;

    const int a_p[4] = {(t * 4) >> 9, (t * 4 + 1) >> 9, (t * 4 + 2) >> 9, (t * 4 + 3) >> 9};
    int a_r[4], a_q[4];
    const __nv_bfloat16* a_src[4];
    uint32_t a_doff[4];
#pragma unroll
    for (int i = 0; i < 4; i++) {
        int idx = t * 4 + i;
        a_r[i] = (idx >> 2) & 127;
        a_q[i] = idx & 3;
        a_src[i] = (a_p[i] ? g_x_lo : g_x_hi) + (size_t)(nbase + a_r[i]) * IN_F + a_q[i] * 8;
        a_doff[i] = (uint32_t)(a_r[i] * (ASTR * 2) + a_q[i] * 16);
    }
    int b_p[2];
    const __nv_bfloat16* b_src[2];
    uint32_t b_doff[2];
#pragma unroll
    for (int i = 0; i < 2; i++) {
        int idx = t * 2 + i;
        b_p[i] = idx >> 8;
        int br = (idx >> 2) & 63, bq = idx & 3;
        b_src[i] = (b_p[i] ? g_WT_lo : g_WT_hi) + ((size_t)h * OUT_F + br) * IN_F + bq * 8;
        b_doff[i] = (uint32_t)(br * (BSTR * 2) + bq * 16);
    }
    const uint32_t smb = smem_u32(sm);

#pragma unroll
    for (int i = 0; i < 4; i++) cp16(smb + WH_A(0, a_p[i]) + a_doff[i], a_src[i]);
#pragma unroll
    for (int i = 0; i < 2; i++) cp16(smb + WH_B(0, b_p[i]) + b_doff[i], b_src[i]);
    cp_commit();

    float acc[8][4];
#pragma unroll
    for (int j = 0; j < 8; j++)
#pragma unroll
        for (int q = 0; q < 4; q++) acc[j][q] = 0.f;

    const uint32_t aRow = (16 * wid + (lane & 15)) * (ASTR * 2) + (lane >> 4) * 16;
    const uint32_t bRow = (lane & 7) * (BSTR * 2) + (lane >> 3) * 16;

    for (int c = 0; c < NCH_W; c++) {
        const int p = c & 1, pn = p ^ 1;
        cp_wait<0>();
        __syncthreads();
        if (c + 1 < NCH_W) {
            const int kb = (c + 1) * KC;
#pragma unroll
            for (int i = 0; i < 4; i++) cp16(smb + WH_A(pn, a_p[i]) + a_doff[i], a_src[i] + kb);
#pragma unroll
            for (int i = 0; i < 2; i++) cp16(smb + WH_B(pn, b_p[i]) + b_doff[i], b_src[i] + kb);
            cp_commit();
        }
        uint32_t afh[2][4], afl[2][4];
        ldm4(afh[0], smb + WH_A(p, 0) + aRow);
        ldm4(afh[1], smb + WH_A(p, 0) + aRow + 32);
        ldm4(afl[0], smb + WH_A(p, 1) + aRow);
        ldm4(afl[1], smb + WH_A(p, 1) + aRow + 32);
#pragma unroll
        for (int j = 0; j < 8; j++) {
            uint32_t bh[4], bl[4];
            ldm4(bh, smb + WH_B(p, 0) + j * 8 * (BSTR * 2) + bRow);
            ldm4(bl, smb + WH_B(p, 1) + j * 8 * (BSTR * 2) + bRow);
            mma_bf16(acc[j], afh[0], bh[0], bh[1]);
            mma_bf16(acc[j], afh[0], bl[0], bl[1]);
            mma_bf16(acc[j], afl[0], bh[0], bh[1]);
            mma_bf16(acc[j], afh[1], bh[2], bh[3]);
            mma_bf16(acc[j], afh[1], bl[2], bl[3]);
            mma_bf16(acc[j], afl[1], bh[2], bh[3]);
        }
        __syncthreads();
    }

    // ---------- fused epilogue ----------
    const int g = lane >> 2;
    const int c2 = (lane & 3) * 2;
    const int row0 = nbase + 16 * wid + g;
    const int row1 = row0 + 8;

    float* o0 = g_Wh + ((size_t)h * N_NODES + row0) * OUT_F + c2;
    float* o1 = g_Wh + ((size_t)h * N_NODES + row1) * OUT_F + c2;
#pragma unroll
    for (int j = 0; j < 8; j++) {
        *(float2*)(o0 + j * 8) = make_float2(acc[j][0], acc[j][1]);
        *(float2*)(o1 + j * 8) = make_float2(acc[j][2], acc[j][3]);
    }

    __half* T = (__half*)(sm + WH_T);
    float* av = (float*)(sm + WH_AV);
    if (t < 64) {
        av[t] = a1v[h * OUT_F + t];
        av[64 + t] = a2v[h * OUT_F + t];
    }
    const int ml0 = 16 * wid + g;
#pragma unroll
    for (int j = 0; j < 8; j++) {
        int o = c2 + j * 8;
        T[o * 136 + ml0] = __float2half(acc[j][0]);
        T[(o + 1) * 136 + ml0] = __float2half(acc[j][1]);
        T[o * 136 + ml0 + 8] = __float2half(acc[j][2]);
        T[(o + 1) * 136 + ml0 + 8] = __float2half(acc[j][3]);
    }
    __syncthreads();

#pragma unroll
    for (int i = 0; i < 4; i++) {
        int idx = t * 4 + i;
        int o = idx >> 4, q = idx & 15;
        uint4 v = *(const uint4*)(T + o * 136 + q * 8);
        *(uint4*)(g_WhT_h16 + ((size_t)h * OUT_F + o) * N_NODES + nbase + q * 8) = v;
    }

    float f10 = 0.f, f20 = 0.f, f11 = 0.f, f21 = 0.f;
#pragma unroll
    for (int j = 0; j < 8; j++) {
        int o = c2 + j * 8;
        float a1x = av[o], a1y = av[o + 1];
        float a2x = av[64 + o], a2y = av[64 + o + 1];
        f10 += acc[j][0] * a1x + acc[j][1] * a1y;
        f20 += acc[j][0] * a2x + acc[j][1] * a2y;
        f11 += acc[j][2] * a1x + acc[j][3] * a1y;
        f21 += acc[j][2] * a2x + acc[j][3] * a2y;
    }
#pragma unroll
    for (int off = 1; off <= 2; off <<= 1) {
        f10 += __shfl_xor_sync(0xffffffffu, f10, off);
        f20 += __shfl_xor_sync(0xffffffffu, f20, off);
        f11 += __shfl_xor_sync(0xffffffffu, f11, off);
        f21 += __shfl_xor_sync(0xffffffffu, f21, off);
    }
    if ((lane & 3) == 0) {
        int i0 = h * N_NODES + row0;
        int i1 = h * N_NODES + row1;
        g_f1[i0] = f10;
        g_f2[i0] = f20;
        g_P2[i0] = expf(f20);
        g_Q2[i0] = expf(ALPHA * f20);
        g_f1[i1] = f11;
        g_f2[i1] = f21;
        g_P2[i1] = expf(f21);
        g_Q2[i1] = expf(ALPHA * f21);
    }
}

// ---------------- kernel: per-head max of f2 + pack fp16 tables ----------------
__global__ __launch_bounds__(256) void maxf2_kernel() {
    __shared__ float red[256];
    const int h = blockIdx.x, t = threadIdx.x;
    float m = -3.4e38f;
#pragma unroll
    for (int i = 0; i < 16; i++) m = fmaxf(m, g_f2[h * N_NODES + t + i * 256]);
    red[t] = m;

    // pack {P2,Q2} as half2 pairs: thread t covers m = t*16 .. t*16+15
    const int bm = h * N_NODES + t * 16;
#pragma unroll
    for (int i = 0; i < 4; i++) {
        float4 pp = *(const float4*)(g_P2 + bm + i * 4);
        float4 qq = *(const float4*)(g_Q2 + bm + i * 4);
        uint4 v;
        v.x = h2bits(__floats2half2_rn(pp.x, pp.y));
        v.y = h2bits(__floats2half2_rn(qq.x, qq.y));
        v.z = h2bits(__floats2half2_rn(pp.z, pp.w));
        v.w = h2bits(__floats2half2_rn(qq.z, qq.w));
        *(uint4*)(g_tab2 + (size_t)h * (N_NODES / 2) + t * 8 + i * 2) = v;
    }

    __syncthreads();
    for (int s = 128; s; s >>= 1) {
        if (t < s) red[t] = fmaxf(red[t], red[t + s]);
        __syncthreads();
    }
    if (t == 0) g_mx[h] = red[0];
}

// ---------------- kernel: fp16 HMMA aggregation, register-fragment A ----------------
// 128 rows x 64 cols per CTA, 512 threads / 16 warps, warp tile 16x32.
// A fragments (attention weights) generated in registers: w = max(P1*P2, Q1*Q2),
// masked by adjacency; D via all-ones-B MMA (exact fp32).
__global__ __launch_bounds__(512, 2) void gat_mma_kernel(float* __restrict__ out) {
    extern __shared__ __align__(16) char sm[];
    const int t = threadIdx.x;
    const int wid = t >> 5, lane = t & 31;
    const int h = blockIdx.y;
    const int nbase = blockIdx.x * GAT_RT;
    const int hN = h * N_NODES;
    const uint32_t smb = smem_u32(sm);

    const int rgrp = wid & 7;        // 16-row group
    const int chalf = wid >> 3;      // 32-col half
    const int g = lane >> 2;
    const int c2 = (lane & 3) * 2;
    const int R0l = rgrp * 16 + g;   // CTA-local rows this lane owns
    const int R1l = R0l + 8;

    // per-row P1/Q1 as broadcast half2 (exp1 folded in; max-shift per row)
    const float mxv = g_mx[h];
    const float f1a = g_f1[hN + nbase + R0l];
    const float f1b = g_f1[hN + nbase + R1l];
    const float sMa = f1a + mxv, Ma = sMa > 0.f ? sMa : ALPHA * sMa;
    const float sMb = f1b + mxv, Mb = sMb > 0.f ? sMb : ALPHA * sMb;
    const __half2 hP1a = __half2half2(__float2half_rn(expf(f1a - Ma)));
    const __half2 hQ1a = __half2half2(__float2half_rn(expf(ALPHA * f1a - Ma)));
    const __half2 hP1b = __half2half2(__float2half_rn(expf(f1b - Mb)));
    const __half2 hQ1b = __half2half2(__float2half_rn(expf(ALPHA * f1b - Mb)));

    // B staging: 512 quads ([64 o][8 quads]), 1 per thread
    const __half* whTh = g_WhT_h16 + ((size_t)h * OUT_F) * N_NODES;
    const int br = t >> 3, bq = t & 7;
    const __half* b_src = whTh + (size_t)br * N_NODES + bq * 8;
    const uint32_t b_doff = (uint32_t)(br * (AST2 * 2) + bq * 16);

    const uint2* tab_src = g_tab2 + (size_t)h * (N_NODES / 2);
    const unsigned* adj_base = g_adjbits + (size_t)nbase * (N_NODES / 32);

    // ---- prologue: B(0), adj(0), tab(0), tab(1) ----
    cp16(smb + GB_B(0) + b_doff, b_src);
    if (t < 128) cp8(smb + GB_ADJ(0) + t * 8, adj_base + (size_t)t * (N_NODES / 32));
    if (t < 16) {
        cp16(smb + GB_TAB(0) + t * 16, tab_src + t * 2);
        cp16(smb + GB_TAB(1) + t * 16, tab_src + 32 + t * 2);
    }
    cp_commit();

    float acc[4][4];
#pragma unroll
    for (int j = 0; j < 4; j++)
#pragma unroll
        for (int e = 0; e < 4; e++) acc[j][e] = 0.f;
    float acc_d[4] = {0.f, 0.f, 0.f, 0.f};

    const int jbase = chalf * 32;
    const uint32_t bOff = (jbase + (lane & 7)) * (AST2 * 2) + (lane >> 3) * 16;
    const uint32_t ONE2 = 0x3C003C00u;   // half2(1.0, 1.0)

    for (int c = 0; c < NCH2; c++) {
        const int p = c & 1, pn = p ^ 1;
        cp_wait<0>();
        __syncthreads();

        if (c + 1 < NCH2) {
            cp16(smb + GB_B(pn) + b_doff, b_src + (c + 1) * KC2);
            if (t < 128)
                cp8(smb + GB_ADJ(pn) + t * 8,
                    adj_base + (size_t)t * (N_NODES / 32) + (c + 1) * 2);
            if (c + 2 < NCH2 && t < 16)
                cp16(smb + GB_TAB((c + 2) % 3) + t * 16, tab_src + (c + 2) * 32 + t * 2);
            cp_commit();
        }

        // ---- generate A fragments in registers ----
        const uint2 adjA = *(const uint2*)(sm + GB_ADJ(p) + R0l * 8);
        const uint2 adjB = *(const uint2*)(sm + GB_ADJ(p) + R1l * 8);
        const char* tabp = sm + GB_TAB(c % 3);
        uint32_t af[4][4];
#pragma unroll
        for (int s = 0; s < 4; s++) {
            const unsigned wordA = (s >= 2) ? adjA.y : adjA.x;
            const unsigned wordB = (s >= 2) ? adjB.y : adjB.x;
#pragma unroll
            for (int d = 0; d < 2; d++) {
                uint2 pq = *(const uint2*)(tabp + (8 * s + 4 * d + (lane & 3)) * 8);
                __half2 P2 = *reinterpret_cast<__half2*>(&pq.x);
                __half2 Q2 = *reinterpret_cast<__half2*>(&pq.y);
                __half2 wa = __hmax2(__hmul2(hP1a, P2), __hmul2(hQ1a, Q2));
                __half2 wb = __hmax2(__hmul2(hP1b, P2), __hmul2(hQ1b, Q2));
                const int pbit = ((16 * s + 8 * d) & 31) + c2;
                unsigned va = wordA >> pbit;
                unsigned vb = wordB >> pbit;
                unsigned ma = ((va & 1u) ? 0xFFFFu : 0u) | ((va & 2u) ? 0xFFFF0000u : 0u);
                unsigned mb = ((vb & 1u) ? 0xFFFFu : 0u) | ((vb & 2u) ? 0xFFFF0000u : 0u);
                af[s][2 * d] = h2bits(wa) & ma;
                af[s][2 * d + 1] = h2bits(wb) & mb;
            }
        }

        // ---- MMA on B buffer p ----
#pragma unroll
        for (int j = 0; j < 4; j++) {
            uint32_t b0[4], b1[4];
            const uint32_t bj = smb + GB_B(p) + j * 8 * (AST2 * 2) + bOff;
            ldm4(b0, bj);
            ldm4(b1, bj + 64);
            mma_f16(acc[j], af[0], b0[0], b0[1]);
            mma_f16(acc[j], af[1], b0[2], b0[3]);
            mma_f16(acc[j], af[2], b1[0], b1[1]);
            mma_f16(acc[j], af[3], b1[2], b1[3]);
        }
        // denominator via ones-column MMA (exact fp32 row sums)
        mma_f16(acc_d, af[0], ONE2, ONE2);
        mma_f16(acc_d, af[1], ONE2, ONE2);
        mma_f16(acc_d, af[2], ONE2, ONE2);
        mma_f16(acc_d, af[3], ONE2, ONE2);
    }

    // ---- epilogue: normalize by per-row D from acc_d ----
    const float inv0 = 1.0f / acc_d[0];
    const float inv1 = 1.0f / acc_d[2];
    float* o0 = out + (size_t)(nbase + R0l) * (HEADS * OUT_F) + h * OUT_F + jbase + c2;
    float* o1 = out + (size_t)(nbase + R1l) * (HEADS * OUT_F) + h * OUT_F + jbase + c2;
#pragma unroll
    for (int j = 0; j < 4; j++) {
        *(float2*)(o0 + j * 8) = make_float2(acc[j][0] * inv0, acc[j][1] * inv0);
        *(float2*)(o1 + j * 8) = make_float2(acc[j][2] * inv1, acc[j][3] * inv1);
    }
}

// ---------------- launch ----------------
extern "C" void kernel_launch(void* const* d_in, const int* in_sizes, int n_in,
                              void* d_out, int out_size) {
    const float* x   = (const float*)d_in[0];
    const int*   adj = (const int*)d_in[1];
    const float* W   = (const float*)d_in[2];
    const float* a1  = (const float*)d_in[3];
    const float* a2  = (const float*)d_in[4];
    float* out = (float*)d_out;

    cudaFuncSetAttribute(wh_mma_kernel, cudaFuncAttributeMaxDynamicSharedMemorySize,
                         WH_SMEM);
    cudaFuncSetAttribute(gat_mma_kernel, cudaFuncAttributeMaxDynamicSharedMemorySize,
                         GB_SMEM);

    prep_kernel<<<3080, 256>>>(adj, x, W);

    dim3 gW(N_NODES / RT, HEADS);
    wh_mma_kernel<<<gW, 256, WH_SMEM>>>(a1, a2);

    maxf2_kernel<<<HEADS, 256>>>();

    dim3 gD(N_NODES / GAT_RT, HEADS);
    gat_mma_kernel<<<gD, 512, GB_SMEM>>>(out);
}

// round 16
// speedup vs baseline: 2.0551x; 1.1256x over previous
#include <cuda_runtime.h>
#include <cuda_bf16.h>
#include <cuda_fp16.h>
#include <cstdint>

#define N_NODES 4096
#define IN_F 512
#define OUT_F 64
#define HEADS 8
#define ALPHA 0.2f

#define RT 128                 // rows per CTA (wh kernel)
#define KC 32                  // k per chunk (wh kernel)
#define NCH_W (IN_F / KC)      // 16 chunks (wh)
#define ASTR 40                // padded bf16 row stride (80 B) (wh kernel)
#define BSTR 40

// ---- wh dynamic smem offsets ----
#define WH_A(buf, prec) ((buf) * 20480 + (prec) * 10240)
#define WH_B(buf, prec) (40960 + (buf) * 10240 + (prec) * 5120)
#define WH_T 0                  // epilogue transpose tile [64][136] fp16 (17408 B)
#define WH_AV 18432             // epilogue a1/a2 staging (128 floats)
#define WH_SMEM 61440

// ---- gat (fp16, 128x64 tile, 512 threads, KC2=64, register-fragment A) ----
#define GAT_RT 128
#define KC2 64
#define NCH2 (N_NODES / KC2)   // 64 chunks
#define AST2 72                // fp16 stride (144 B) for B tile
#define GB_B(buf)  ((buf) * 9216)            // [64][72] fp16, 2 bufs
#define GB_TAB(tb) (18432 + (tb) * 256)      // 32 pairs x {P2h2,Q2h2}, 3 bufs
#define GB_ADJ(buf) (19200 + (buf) * 1024)   // 128 rows x 8 B, 2 bufs
#define GB_SMEM 21504

// ---------------- scratch (device globals; no allocation) ----------------
__device__ __align__(16) float g_Wh[HEADS * N_NODES * OUT_F];          // 8 MB [h][n][o]
__device__ float g_f1[HEADS * N_NODES];
__device__ float g_f2[HEADS * N_NODES];
__device__ float g_P2[HEADS * N_NODES];   // exp(f2)
__device__ float g_Q2[HEADS * N_NODES];   // exp(a*f2)
__device__ float g_mx[HEADS];             // per-head max f2
__device__ __align__(16) uint2 g_tab2[HEADS * (N_NODES / 2)];          // {P2h2,Q2h2}/pair
__device__ __align__(16) unsigned g_adjbits[N_NODES * (N_NODES / 32)]; // 2 MB
__device__ __align__(16) __half g_WhT_h16[HEADS * OUT_F * N_NODES];    // 4 MB [h][o][m]
__device__ __align__(16) __nv_bfloat16 g_x_hi[N_NODES * IN_F];         // 4 MB [n][k]
__device__ __align__(16) __nv_bfloat16 g_x_lo[N_NODES * IN_F];
__device__ __align__(16) __nv_bfloat16 g_WT_hi[HEADS * OUT_F * IN_F];  // 512 KB
__device__ __align__(16) __nv_bfloat16 g_WT_lo[HEADS * OUT_F * IN_F];

// ---------------- helpers ----------------
__device__ __forceinline__ uint32_t smem_u32(const void* p) {
    uint32_t a;
    asm("{ .reg .u64 t; cvta.to.shared.u64 t, %1; cvt.u32.u64 %0, t; }" : "=r"(a) : "l"(p));
    return a;
}
__device__ __forceinline__ void cp16(uint32_t dst, const void* src) {
    asm volatile("cp.async.cg.shared.global [%0], [%1], 16;" :: "r"(dst), "l"(src) : "memory");
}
__device__ __forceinline__ void cp8(uint32_t dst, const void* src) {
    asm volatile("cp.async.ca.shared.global [%0], [%1], 8;" :: "r"(dst), "l"(src) : "memory");
}
__device__ __forceinline__ void cp_commit() {
    asm volatile("cp.async.commit_group;" ::: "memory");
}
template <int N>
__device__ __forceinline__ void cp_wait() {
    asm volatile("cp.async.wait_group %0;" :: "n"(N) : "memory");
}
__device__ __forceinline__ void ldm4(uint32_t* r, uint32_t addr) {
    asm volatile("ldmatrix.sync.aligned.m8n8.x4.shared.b16 {%0,%1,%2,%3}, [%4];"
                 : "=r"(r[0]), "=r"(r[1]), "=r"(r[2]), "=r"(r[3]) : "r"(addr) : "memory");
}
__device__ __forceinline__ void mma_bf16(float* c, const uint32_t* a, uint32_t b0,
                                         uint32_t b1) {
    asm("mma.sync.aligned.m16n8k16.row.col.f32.bf16.bf16.f32 "
        "{%0,%1,%2,%3}, {%4,%5,%6,%7}, {%8,%9}, {%0,%1,%2,%3};"
        : "+f"(c[0]), "+f"(c[1]), "+f"(c[2]), "+f"(c[3])
        : "r"(a[0]), "r"(a[1]), "r"(a[2]), "r"(a[3]), "r"(b0), "r"(b1));
}
__device__ __forceinline__ void mma_f16(float* c, const uint32_t* a, uint32_t b0,
                                        uint32_t b1) {
    asm("mma.sync.aligned.m16n8k16.row.col.f32.f16.f16.f32 "
        "{%0,%1,%2,%3}, {%4,%5,%6,%7}, {%8,%9}, {%0,%1,%2,%3};"
        : "+f"(c[0]), "+f"(c[1]), "+f"(c[2]), "+f"(c[3])
        : "r"(a[0]), "r"(a[1]), "r"(a[2]), "r"(a[3]), "r"(b0), "r"(b1));
}
__device__ __forceinline__ unsigned prmt(unsigned a, unsigned b, unsigned s) {
    unsigned d;
    asm("prmt.b32 %0, %1, %2, %3;" : "=r"(d) : "r"(a), "r"(b), "r"(s));
    return d;
}
__device__ __forceinline__ void split_pair(float x, float y, unsigned& hi, unsigned& lo) {
    __nv_bfloat162 h2 = __float22bfloat162_rn(make_float2(x, y));
    float2 hf = __bfloat1622float2(h2);
    __nv_bfloat162 l2 = __float22bfloat162_rn(make_float2(x - hf.x, y - hf.y));
    hi = *reinterpret_cast<unsigned*>(&h2);
    lo = *reinterpret_cast<unsigned*>(&l2);
}
__device__ __forceinline__ unsigned h2bits(__half2 v) {
    return *reinterpret_cast<unsigned*>(&v);
}

// ---------------- kernel: fused prep (bitpack | xsplit | wsplit) ----------------
__global__ __launch_bounds__(256) void prep_kernel(const int* __restrict__ adj,
                                                   const float* __restrict__ x,
                                                   const float* __restrict__ W) {
    const int b = blockIdx.x;
    const int tid = threadIdx.x;
    if (b < 2048) {
        int t = b * 256 + tid;
        const int4* p = (const int4*)adj + (size_t)t * 8;
        unsigned w = 0;
#pragma unroll
        for (int i = 0; i < 8; i++) {
            int4 v = p[i];
            w |= (v.x > 0 ? 1u : 0u) << (4 * i);
            w |= (v.y > 0 ? 1u : 0u) << (4 * i + 1);
            w |= (v.z > 0 ? 1u : 0u) << (4 * i + 2);
            w |= (v.w > 0 ? 1u : 0u) << (4 * i + 3);
        }
        g_adjbits[t] = w;
    } else if (b < 3072) {
        int gid = (b - 2048) * 256 + tid;
        const float4* xp = (const float4*)x + gid * 2;
        float4 v0 = xp[0], v1 = xp[1];
        float f[8] = {v0.x, v0.y, v0.z, v0.w, v1.x, v1.y, v1.z, v1.w};
        unsigned hw[4], lw[4];
#pragma unroll
        for (int i = 0; i < 4; i++) split_pair(f[2 * i], f[2 * i + 1], hw[i], lw[i]);
        *(uint4*)(g_x_hi + (size_t)gid * 8) = make_uint4(hw[0], hw[1], hw[2], hw[3]);
        *(uint4*)(g_x_lo + (size_t)gid * 8) = make_uint4(lw[0], lw[1], lw[2], lw[3]);
    } else {
        const int h = b - 3072;
#pragma unroll 4
        for (int i = 0; i < 128; i++) {
            int lin = i * 256 + tid;
            int o = lin >> 9, k = lin & 511;
            float v = W[((size_t)h * IN_F + k) * OUT_F + o];
            __nv_bfloat16 hb = __float2bfloat16(v);
            __nv_bfloat16 lb = __float2bfloat16(v - __bfloat162float(hb));
            size_t d = ((size_t)h * OUT_F + o) * IN_F + k;
            g_WT_hi[d] = hb;
            g_WT_lo[d] = lb;
        }
    }
}

// ---------------- kernel: Wh = x @ W via HMMA + fused f1/f2/exp/WhT epilogue ----------------
__global__ __launch_bounds__(256, 2) void wh_mma_kernel(const float* __restrict__ a1v,
                                                        const float* __restrict__ a2v) {
    extern __shared__ __align__(16) char sm[];
    const int t = threadIdx.x;
    const int wid = t >> 5, lane = t & 31;
    const int h = blockIdx.y;
    const int nbase = blockIdx.x * RT;

    const int a_p[4] = {(t * 4) >> 9, (t * 4 + 1) >> 9, (t * 4 + 2) >> 9, (t * 4 + 3) >> 9};
    int a_r[4], a_q[4];
    const __nv_bfloat16* a_src[4];
    uint32_t a_doff[4];
#pragma unroll
    for (int i = 0; i < 4; i++) {
        int idx = t * 4 + i;
        a_r[i] = (idx >> 2) & 127;
        a_q[i] = idx & 3;
        a_src[i] = (a_p[i] ? g_x_lo : g_x_hi) + (size_t)(nbase + a_r[i]) * IN_F + a_q[i] * 8;
        a_doff[i] = (uint32_t)(a_r[i] * (ASTR * 2) + a_q[i] * 16);
    }
    int b_p[2];
    const __nv_bfloat16* b_src[2];
    uint32_t b_doff[2];
#pragma unroll
    for (int i = 0; i < 2; i++) {
        int idx = t * 2 + i;
        b_p[i] = idx >> 8;
        int br = (idx >> 2) & 63, bq = idx & 3;
        b_src[i] = (b_p[i] ? g_WT_lo : g_WT_hi) + ((size_t)h * OUT_F + br) * IN_F + bq * 8;
        b_doff[i] = (uint32_t)(br * (BSTR * 2) + bq * 16);
    }
    const uint32_t smb = smem_u32(sm);

#pragma unroll
    for (int i = 0; i < 4; i++) cp16(smb + WH_A(0, a_p[i]) + a_doff[i], a_src[i]);
#pragma unroll
    for (int i = 0; i < 2; i++) cp16(smb + WH_B(0, b_p[i]) + b_doff[i], b_src[i]);
    cp_commit();

    float acc[8][4];
#pragma unroll
    for (int j = 0; j < 8; j++)
#pragma unroll
        for (int q = 0; q < 4; q++) acc[j][q] = 0.f;

    const uint32_t aRow = (16 * wid + (lane & 15)) * (ASTR * 2) + (lane >> 4) * 16;
    const uint32_t bRow = (lane & 7) * (BSTR * 2) + (lane >> 3) * 16;

    for (int c = 0; c < NCH_W; c++) {
        const int p = c & 1, pn = p ^ 1;
        cp_wait<0>();
        __syncthreads();
        if (c + 1 < NCH_W) {
            const int kb = (c + 1) * KC;
#pragma unroll
            for (int i = 0; i < 4; i++) cp16(smb + WH_A(pn, a_p[i]) + a_doff[i], a_src[i] + kb);
#pragma unroll
            for (int i = 0; i < 2; i++) cp16(smb + WH_B(pn, b_p[i]) + b_doff[i], b_src[i] + kb);
            cp_commit();
        }
        uint32_t afh[2][4], afl[2][4];
        ldm4(afh[0], smb + WH_A(p, 0) + aRow);
        ldm4(afh[1], smb + WH_A(p, 0) + aRow + 32);
        ldm4(afl[0], smb + WH_A(p, 1) + aRow);
        ldm4(afl[1], smb + WH_A(p, 1) + aRow + 32);
#pragma unroll
        for (int j = 0; j < 8; j++) {
            uint32_t bh[4], bl[4];
            ldm4(bh, smb + WH_B(p, 0) + j * 8 * (BSTR * 2) + bRow);
            ldm4(bl, smb + WH_B(p, 1) + j * 8 * (BSTR * 2) + bRow);
            mma_bf16(acc[j], afh[0], bh[0], bh[1]);
            mma_bf16(acc[j], afh[0], bl[0], bl[1]);
            mma_bf16(acc[j], afl[0], bh[0], bh[1]);
            mma_bf16(acc[j], afh[1], bh[2], bh[3]);
            mma_bf16(acc[j], afh[1], bl[2], bl[3]);
            mma_bf16(acc[j], afl[1], bh[2], bh[3]);
        }
        __syncthreads();
    }

    // ---------- fused epilogue ----------
    const int g = lane >> 2;
    const int c2 = (lane & 3) * 2;
    const int row0 = nbase + 16 * wid + g;
    const int row1 = row0 + 8;

    float* o0 = g_Wh + ((size_t)h * N_NODES + row0) * OUT_F + c2;
    float* o1 = g_Wh + ((size_t)h * N_NODES + row1) * OUT_F + c2;
#pragma unroll
    for (int j = 0; j < 8; j++) {
        *(float2*)(o0 + j * 8) = make_float2(acc[j][0], acc[j][1]);
        *(float2*)(o1 + j * 8) = make_float2(acc[j][2], acc[j][3]);
    }

    __half* T = (__half*)(sm + WH_T);
    float* av = (float*)(sm + WH_AV);
    if (t < 64) {
        av[t] = a1v[h * OUT_F + t];
        av[64 + t] = a2v[h * OUT_F + t];
    }
    const int ml0 = 16 * wid + g;
#pragma unroll
    for (int j = 0; j < 8; j++) {
        int o = c2 + j * 8;
        T[o * 136 + ml0] = __float2half(acc[j][0]);
        T[(o + 1) * 136 + ml0] = __float2half(acc[j][1]);
        T[o * 136 + ml0 + 8] = __float2half(acc[j][2]);
        T[(o + 1) * 136 + ml0 + 8] = __float2half(acc[j][3]);
    }
    __syncthreads();

#pragma unroll
    for (int i = 0; i < 4; i++) {
        int idx = t * 4 + i;
        int o = idx >> 4, q = idx & 15;
        uint4 v = *(const uint4*)(T + o * 136 + q * 8);
        *(uint4*)(g_WhT_h16 + ((size_t)h * OUT_F + o) * N_NODES + nbase + q * 8) = v;
    }

    float f10 = 0.f, f20 = 0.f, f11 = 0.f, f21 = 0.f;
#pragma unroll
    for (int j = 0; j < 8; j++) {
        int o = c2 + j * 8;
        float a1x = av[o], a1y = av[o + 1];
        float a2x = av[64 + o], a2y = av[64 + o + 1];
        f10 += acc[j][0] * a1x + acc[j][1] * a1y;
        f20 += acc[j][0] * a2x + acc[j][1] * a2y;
        f11 += acc[j][2] * a1x + acc[j][3] * a1y;
        f21 += acc[j][2] * a2x + acc[j][3] * a2y;
    }
#pragma unroll
    for (int off = 1; off <= 2; off <<= 1) {
        f10 += __shfl_xor_sync(0xffffffffu, f10, off);
        f20 += __shfl_xor_sync(0xffffffffu, f20, off);
        f11 += __shfl_xor_sync(0xffffffffu, f11, off);
        f21 += __shfl_xor_sync(0xffffffffu, f21, off);
    }
    if ((lane & 3) == 0) {
        int i0 = h * N_NODES + row0;
        int i1 = h * N_NODES + row1;
        g_f1[i0] = f10;
        g_f2[i0] = f20;
        g_P2[i0] = expf(f20);
        g_Q2[i0] = expf(ALPHA * f20);
        g_f1[i1] = f11;
        g_f2[i1] = f21;
        g_P2[i1] = expf(f21);
        g_Q2[i1] = expf(ALPHA * f21);
    }
}

// ---------------- kernel: per-head max of f2 + pack fp16 tables ----------------
__global__ __launch_bounds__(256) void maxf2_kernel() {
    __shared__ float red[256];
    const int h = blockIdx.x, t = threadIdx.x;
    float m = -3.4e38f;
#pragma unroll
    for (int i = 0; i < 16; i++) m = fmaxf(m, g_f2[h * N_NODES + t + i * 256]);
    red[t] = m;

    const int bm = h * N_NODES + t * 16;
#pragma unroll
    for (int i = 0; i < 4; i++) {
        float4 pp = *(const float4*)(g_P2 + bm + i * 4);
        float4 qq = *(const float4*)(g_Q2 + bm + i * 4);
        uint4 v;
        v.x = h2bits(__floats2half2_rn(pp.x, pp.y));
        v.y = h2bits(__floats2half2_rn(qq.x, qq.y));
        v.z = h2bits(__floats2half2_rn(pp.z, pp.w));
        v.w = h2bits(__floats2half2_rn(qq.z, qq.w));
        *(uint4*)(g_tab2 + (size_t)h * (N_NODES / 2) + t * 8 + i * 2) = v;
    }

    __syncthreads();
    for (int s = 128; s; s >>= 1) {
        if (t < s) red[t] = fmaxf(red[t], red[t + s]);
        __syncthreads();
    }
    if (t == 0) g_mx[h] = red[0];
}

// ---------------- kernel: fp16 HMMA aggregation, register-fragment A ----------------
// 128 rows x 64 cols per CTA, 512 threads / 16 warps, warp tile 16x32.
// A fragments generated in registers; adjacency masks via PRMT sign-replication.
__global__ __launch_bounds__(512, 2) void gat_mma_kernel(float* __restrict__ out) {
    extern __shared__ __align__(16) char sm[];
    const int t = threadIdx.x;
    const int wid = t >> 5, lane = t & 31;
    const int h = blockIdx.y;
    const int nbase = blockIdx.x * GAT_RT;
    const int hN = h * N_NODES;
    const uint32_t smb = smem_u32(sm);

    const int rgrp = wid & 7;        // 16-row group
    const int chalf = wid >> 3;      // 32-col half
    const int g = lane >> 2;
    const int c2 = (lane & 3) * 2;
    const int R0l = rgrp * 16 + g;
    const int R1l = R0l + 8;

    // per-row P1/Q1 as broadcast half2 (max-shifted)
    const float mxv = g_mx[h];
    const float f1a = g_f1[hN + nbase + R0l];
    const float f1b = g_f1[hN + nbase + R1l];
    const float sMa = f1a + mxv, Ma = sMa > 0.f ? sMa : ALPHA * sMa;
    const float sMb = f1b + mxv, Mb = sMb > 0.f ? sMb : ALPHA * sMb;
    const __half2 hP1a = __half2half2(__float2half_rn(expf(f1a - Ma)));
    const __half2 hQ1a = __half2half2(__float2half_rn(expf(ALPHA * f1a - Ma)));
    const __half2 hP1b = __half2half2(__float2half_rn(expf(f1b - Mb)));
    const __half2 hQ1b = __half2half2(__float2half_rn(expf(ALPHA * f1b - Mb)));

    // B staging: 512 quads, 1 per thread
    const __half* whTh = g_WhT_h16 + ((size_t)h * OUT_F) * N_NODES;
    const int br = t >> 3, bq = t & 7;
    const __half* b_src = whTh + (size_t)br * N_NODES + bq * 8;
    const uint32_t b_doff = (uint32_t)(br * (AST2 * 2) + bq * 16);

    const uint2* tab_src = g_tab2 + (size_t)h * (N_NODES / 2);
    const unsigned* adj_base = g_adjbits + (size_t)nbase * (N_NODES / 32);

    // ---- prologue: B(0), adj(0), tab(0), tab(1) ----
    cp16(smb + GB_B(0) + b_doff, b_src);
    if (t < 128) cp8(smb + GB_ADJ(0) + t * 8, adj_base + (size_t)t * (N_NODES / 32));
    if (t < 16) {
        cp16(smb + GB_TAB(0) + t * 16, tab_src + t * 2);
        cp16(smb + GB_TAB(1) + t * 16, tab_src + 32 + t * 2);
    }
    cp_commit();

    float acc[4][4];
#pragma unroll
    for (int j = 0; j < 4; j++)
#pragma unroll
        for (int e = 0; e < 4; e++) acc[j][e] = 0.f;
    float acc_d[4] = {0.f, 0.f, 0.f, 0.f};

    const int jbase = chalf * 32;
    const uint32_t bOff = (jbase + (lane & 7)) * (AST2 * 2) + (lane >> 3) * 16;
    const uint32_t ONE2 = 0x3C003C00u;

    for (int c = 0; c < NCH2; c++) {
        const int p = c & 1, pn = p ^ 1;
        cp_wait<0>();
        __syncthreads();

        if (c + 1 < NCH2) {
            cp16(smb + GB_B(pn) + b_doff, b_src + (c + 1) * KC2);
            if (t < 128)
                cp8(smb + GB_ADJ(pn) + t * 8,
                    adj_base + (size_t)t * (N_NODES / 32) + (c + 1) * 2);
            if (c + 2 < NCH2 && t < 16)
                cp16(smb + GB_TAB((c + 2) % 3) + t * 16, tab_src + (c + 2) * 32 + t * 2);
            cp_commit();
        }

        // ---- A fragments in registers; masks via PRMT sign-replication ----
        const uint2 adjA = *(const uint2*)(sm + GB_ADJ(p) + R0l * 8);
        const uint2 adjB = *(const uint2*)(sm + GB_ADJ(p) + R1l * 8);
        // t = word >> c2: mask bits of fragment byte k live at bits {8k, 8k+1}
        const unsigned tAx = adjA.x >> c2, tAy = adjA.y >> c2;
        const unsigned tBx = adjB.x >> c2, tBy = adjB.y >> c2;
        const unsigned loAx = tAx << 7, hiAx = tAx << 6;
        const unsigned loAy = tAy << 7, hiAy = tAy << 6;
        const unsigned loBx = tBx << 7, hiBx = tBx << 6;
        const unsigned loBy = tBy << 7, hiBy = tBy << 6;
        const char* tabp = sm + GB_TAB(c % 3) + (lane & 3) * 8;

        uint32_t af[4][4];
#pragma unroll
        for (int s = 0; s < 4; s++) {
            const unsigned lA = (s >= 2) ? loAy : loAx;
            const unsigned hA = (s >= 2) ? hiAy : hiAx;
            const unsigned lB = (s >= 2) ? loBy : loBx;
            const unsigned hB = (s >= 2) ? hiBy : hiBx;
#pragma unroll
            for (int d = 0; d < 2; d++) {
                const int k = 2 * (s & 1) + d;   // byte index within word
                const unsigned sel = 0xCC88u + 0x1111u * (unsigned)k;
                uint2 pq = *(const uint2*)(tabp + (8 * s + 4 * d) * 8);
                __half2 P2 = *reinterpret_cast<__half2*>(&pq.x);
                __half2 Q2 = *reinterpret_cast<__half2*>(&pq.y);
                __half2 wa = __hmax2(__hmul2(hP1a, P2), __hmul2(hQ1a, Q2));
                __half2 wb = __hmax2(__hmul2(hP1b, P2), __hmul2(hQ1b, Q2));
                af[s][2 * d] = h2bits(wa) & prmt(lA, hA, sel);
                af[s][2 * d + 1] = h2bits(wb) & prmt(lB, hB, sel);
            }
        }

        // ---- MMA on B buffer p ----
#pragma unroll
        for (int j = 0; j < 4; j++) {
            uint32_t b0[4], b1[4];
            const uint32_t bj = smb + GB_B(p) + j * 8 * (AST2 * 2) + bOff;
            ldm4(b0, bj);
            ldm4(b1, bj + 64);
            mma_f16(acc[j], af[0], b0[0], b0[1]);
            mma_f16(acc[j], af[1], b0[2], b0[3]);
            mma_f16(acc[j], af[2], b1[0], b1[1]);
            mma_f16(acc[j], af[3], b1[2], b1[3]);
        }
        mma_f16(acc_d, af[0], ONE2, ONE2);
        mma_f16(acc_d, af[1], ONE2, ONE2);
        mma_f16(acc_d, af[2], ONE2, ONE2);
        mma_f16(acc_d, af[3], ONE2, ONE2);
    }

    const float inv0 = 1.0f / acc_d[0];
    const float inv1 = 1.0f / acc_d[2];
    float* o0 = out + (size_t)(nbase + R0l) * (HEADS * OUT_F) + h * OUT_F + jbase + c2;
    float* o1 = out + (size_t)(nbase + R1l) * (HEADS * OUT_F) + h * OUT_F + jbase + c2;
#pragma unroll
    for (int j = 0; j < 4; j++) {
        *(float2*)(o0 + j * 8) = make_float2(acc[j][0] * inv0, acc[j][1] * inv0);
        *(float2*)(o1 + j * 8) = make_float2(acc[j][2] * inv1, acc[j][3] * inv1);
    }
}

// ---------------- launch ----------------
extern "C" void kernel_launch(void* const* d_in, const int* in_sizes, int n_in,
                              void* d_out, int out_size) {
    const float* x   = (const float*)d_in[0];
    const int*   adj = (const int*)d_in[1];
    const float* W   = (const float*)d_in[2];
    const float* a1  = (const float*)d_in[3];
    const float* a2  = (const float*)d_in[4];
    float* out = (float*)d_out;

    cudaFuncSetAttribute(wh_mma_kernel, cudaFuncAttributeMaxDynamicSharedMemorySize,
                         WH_SMEM);
    cudaFuncSetAttribute(gat_mma_kernel, cudaFuncAttributeMaxDynamicSharedMemorySize,
                         GB_SMEM);

    prep_kernel<<<3080, 256>>>(adj, x, W);

    dim3 gW(N_NODES / RT, HEADS);
    wh_mma_kernel<<<gW, 256, WH_SMEM>>>(a1, a2);

    maxf2_kernel<<<HEADS, 256>>>();

    dim3 gD(N_NODES / GAT_RT, HEADS);
    gat_mma_kernel<<<gD, 512, GB_SMEM>>>(out);
}

// round 17
// speedup vs baseline: 2.0944x; 1.0191x over previous
#include <cuda_runtime.h>
#include <cuda_bf16.h>
#include <cuda_fp16.h>
#include <cstdint>

#define N_NODES 4096
#define IN_F 512
#define OUT_F 64
#define HEADS 8
#define ALPHA 0.2f

#define RT 128                 // rows per CTA (wh kernel)
#define KC 32                  // k per chunk (wh kernel)
#define NCH_W (IN_F / KC)      // 16 chunks (wh)
#define ASTR 40                // padded bf16 row stride (80 B) (wh kernel)
#define BSTR 40

// ---- wh dynamic smem offsets ----
#define WH_A(buf, prec) ((buf) * 20480 + (prec) * 10240)
#define WH_B(buf, prec) (40960 + (buf) * 10240 + (prec) * 5120)
#define WH_T 0                  // epilogue transpose tile [64][136] fp16 (17408 B)
#define WH_AV 18432             // epilogue a1/a2 staging (128 floats)
#define WH_SMEM 61440

// ---- gat (fp16, 128x64 tile, 256 threads, warp tile 32x32, reg-fragment A) ----
#define GAT_RT 128
#define KC2 64
#define NCH2 (N_NODES / KC2)   // 64 chunks
#define AST2 72                // fp16 stride (144 B) for B tile
#define GB_B(buf)  ((buf) * 9216)            // [64][72] fp16, 2 bufs
#define GB_TAB(tb) (18432 + (tb) * 256)      // 32 pairs x {P2h2,Q2h2}, 3 bufs
#define GB_ADJ(buf) (19200 + (buf) * 1024)   // 128 rows x 8 B, 2 bufs
#define GB_SMEM 21504

// ---------------- scratch (device globals; no allocation) ----------------
__device__ __align__(16) float g_Wh[HEADS * N_NODES * OUT_F];          // 8 MB [h][n][o]
__device__ float g_f1[HEADS * N_NODES];
__device__ float g_f2[HEADS * N_NODES];
__device__ float g_P2[HEADS * N_NODES];   // exp(f2)
__device__ float g_Q2[HEADS * N_NODES];   // exp(a*f2)
__device__ float g_mx[HEADS];             // per-head max f2
__device__ __align__(16) uint2 g_tab2[HEADS * (N_NODES / 2)];          // {P2h2,Q2h2}/pair
__device__ __align__(16) unsigned g_adjbits[N_NODES * (N_NODES / 32)]; // 2 MB
__device__ __align__(16) __half g_WhT_h16[HEADS * OUT_F * N_NODES];    // 4 MB [h][o][m]
__device__ __align__(16) __nv_bfloat16 g_x_hi[N_NODES * IN_F];         // 4 MB [n][k]
__device__ __align__(16) __nv_bfloat16 g_x_lo[N_NODES * IN_F];
__device__ __align__(16) __nv_bfloat16 g_WT_hi[HEADS * OUT_F * IN_F];  // 512 KB
__device__ __align__(16) __nv_bfloat16 g_WT_lo[HEADS * OUT_F * IN_F];

// ---------------- helpers ----------------
__device__ __forceinline__ uint32_t smem_u32(const void* p) {
    uint32_t a;
    asm("{ .reg .u64 t; cvta.to.shared.u64 t, %1; cvt.u32.u64 %0, t; }" : "=r"(a) : "l"(p));
    return a;
}
__device__ __forceinline__ void cp16(uint32_t dst, const void* src) {
    asm volatile("cp.async.cg.shared.global [%0], [%1], 16;" :: "r"(dst), "l"(src) : "memory");
}
__device__ __forceinline__ void cp8(uint32_t dst, const void* src) {
    asm volatile("cp.async.ca.shared.global [%0], [%1], 8;" :: "r"(dst), "l"(src) : "memory");
}
__device__ __forceinline__ void cp_commit() {
    asm volatile("cp.async.commit_group;" ::: "memory");
}
template <int N>
__device__ __forceinline__ void cp_wait() {
    asm volatile("cp.async.wait_group %0;" :: "n"(N) : "memory");
}
__device__ __forceinline__ void ldm4(uint32_t* r, uint32_t addr) {
    asm volatile("ldmatrix.sync.aligned.m8n8.x4.shared.b16 {%0,%1,%2,%3}, [%4];"
                 : "=r"(r[0]), "=r"(r[1]), "=r"(r[2]), "=r"(r[3]) : "r"(addr) : "memory");
}
__device__ __forceinline__ void mma_bf16(float* c, const uint32_t* a, uint32_t b0,
                                         uint32_t b1) {
    asm("mma.sync.aligned.m16n8k16.row.col.f32.bf16.bf16.f32 "
        "{%0,%1,%2,%3}, {%4,%5,%6,%7}, {%8,%9}, {%0,%1,%2,%3};"
        : "+f"(c[0]), "+f"(c[1]), "+f"(c[2]), "+f"(c[3])
        : "r"(a[0]), "r"(a[1]), "r"(a[2]), "r"(a[3]), "r"(b0), "r"(b1));
}
__device__ __forceinline__ void mma_f16(float* c, const uint32_t* a, uint32_t b0,
                                        uint32_t b1) {
    asm("mma.sync.aligned.m16n8k16.row.col.f32.f16.f16.f32 "
        "{%0,%1,%2,%3}, {%4,%5,%6,%7}, {%8,%9}, {%0,%1,%2,%3};"
        : "+f"(c[0]), "+f"(c[1]), "+f"(c[2]), "+f"(c[3])
        : "r"(a[0]), "r"(a[1]), "r"(a[2]), "r"(a[3]), "r"(b0), "r"(b1));
}
__device__ __forceinline__ unsigned prmt(unsigned a, unsigned b, unsigned s) {
    unsigned d;
    asm("prmt.b32 %0, %1, %2, %3;" : "=r"(d) : "r"(a), "r"(b), "r"(s));
    return d;
}
__device__ __forceinline__ void split_pair(float x, float y, unsigned& hi, unsigned& lo) {
    __nv_bfloat162 h2 = __float22bfloat162_rn(make_float2(x, y));
    float2 hf = __bfloat1622float2(h2);
    __nv_bfloat162 l2 = __float22bfloat162_rn(make_float2(x - hf.x, y - hf.y));
    hi = *reinterpret_cast<unsigned*>(&h2);
    lo = *reinterpret_cast<unsigned*>(&l2);
}
__device__ __forceinline__ unsigned h2bits(__half2 v) {
    return *reinterpret_cast<unsigned*>(&v);
}

// ---------------- kernel: fused prep (bitpack | xsplit | wsplit) ----------------
__global__ __launch_bounds__(256) void prep_kernel(const int* __restrict__ adj,
                                                   const float* __restrict__ x,
                                                   const float* __restrict__ W) {
    const int b = blockIdx.x;
    const int tid = threadIdx.x;
    if (b < 2048) {
        int t = b * 256 + tid;
        const int4* p = (const int4*)adj + (size_t)t * 8;
        unsigned w = 0;
#pragma unroll
        for (int i = 0; i < 8; i++) {
            int4 v = p[i];
            w |= (v.x > 0 ? 1u : 0u) << (4 * i);
            w |= (v.y > 0 ? 1u : 0u) << (4 * i + 1);
            w |= (v.z > 0 ? 1u : 0u) << (4 * i + 2);
            w |= (v.w > 0 ? 1u : 0u) << (4 * i + 3);
        }
        g_adjbits[t] = w;
    } else if (b < 3072) {
        int gid = (b - 2048) * 256 + tid;
        const float4* xp = (const float4*)x + gid * 2;
        float4 v0 = xp[0], v1 = xp[1];
        float f[8] = {v0.x, v0.y, v0.z, v0.w, v1.x, v1.y, v1.z, v1.w};
        unsigned hw[4], lw[4];
#pragma unroll
        for (int i = 0; i < 4; i++) split_pair(f[2 * i], f[2 * i + 1], hw[i], lw[i]);
        *(uint4*)(g_x_hi + (size_t)gid * 8) = make_uint4(hw[0], hw[1], hw[2], hw[3]);
        *(uint4*)(g_x_lo + (size_t)gid * 8) = make_uint4(lw[0], lw[1], lw[2], lw[3]);
    } else {
        const int h = b - 3072;
#pragma unroll 4
        for (int i = 0; i < 128; i++) {
            int lin = i * 256 + tid;
            int o = lin >> 9, k = lin & 511;
            float v = W[((size_t)h * IN_F + k) * OUT_F + o];
            __nv_bfloat16 hb = __float2bfloat16(v);
            __nv_bfloat16 lb = __float2bfloat16(v - __bfloat162float(hb));
            size_t d = ((size_t)h * OUT_F + o) * IN_F + k;
            g_WT_hi[d] = hb;
            g_WT_lo[d] = lb;
        }
    }
}

// ---------------- kernel: Wh = x @ W via HMMA + fused f1/f2/exp/WhT epilogue ----------------
__global__ __launch_bounds__(256, 2) void wh_mma_kernel(const float* __restrict__ a1v,
                                                        const float* __restrict__ a2v) {
    extern __shared__ __align__(16) char sm[];
    const int t = threadIdx.x;
    const int wid = t >> 5, lane = t & 31;
    const int h = blockIdx.y;
    const int nbase = blockIdx.x * RT;

    const int a_p[4] = {(t * 4) >> 9, (t * 4 + 1) >> 9, (t * 4 + 2) >> 9, (t * 4 + 3) >> 9};
    int a_r[4], a_q[4];
    const __nv_bfloat16* a_src[4];
    uint32_t a_doff[4];
#pragma unroll
    for (int i = 0; i < 4; i++) {
        int idx = t * 4 + i;
        a_r[i] = (idx >> 2) & 127;
        a_q[i] = idx & 3;
        a_src[i] = (a_p[i] ? g_x_lo : g_x_hi) + (size_t)(nbase + a_r[i]) * IN_F + a_q[i] * 8;
        a_doff[i] = (uint32_t)(a_r[i] * (ASTR * 2) + a_q[i] * 16);
    }
    int b_p[2];
    const __nv_bfloat16* b_src[2];
    uint32_t b_doff[2];
#pragma unroll
    for (int i = 0; i < 2; i++) {
        int idx = t * 2 + i;
        b_p[i] = idx >> 8;
        int br = (idx >> 2) & 63, bq = idx & 3;
        b_src[i] = (b_p[i] ? g_WT_lo : g_WT_hi) + ((size_t)h * OUT_F + br) * IN_F + bq * 8;
        b_doff[i] = (uint32_t)(br * (BSTR * 2) + bq * 16);
    }
    const uint32_t smb = smem_u32(sm);

#pragma unroll
    for (int i = 0; i < 4; i++) cp16(smb + WH_A(0, a_p[i]) + a_doff[i], a_src[i]);
#pragma unroll
    for (int i = 0; i < 2; i++) cp16(smb + WH_B(0, b_p[i]) + b_doff[i], b_src[i]);
    cp_commit();

    float acc[8][4];
#pragma unroll
    for (int j = 0; j < 8; j++)
#pragma unroll
        for (int q = 0; q < 4; q++) acc[j][q] = 0.f;

    const uint32_t aRow = (16 * wid + (lane & 15)) * (ASTR * 2) + (lane >> 4) * 16;
    const uint32_t bRow = (lane & 7) * (BSTR * 2) + (lane >> 3) * 16;

    for (int c = 0; c < NCH_W; c++) {
        const int p = c & 1, pn = p ^ 1;
        cp_wait<0>();
        __syncthreads();
        if (c + 1 < NCH_W) {
            const int kb = (c + 1) * KC;
#pragma unroll
            for (int i = 0; i < 4; i++) cp16(smb + WH_A(pn, a_p[i]) + a_doff[i], a_src[i] + kb);
#pragma unroll
            for (int i = 0; i < 2; i++) cp16(smb + WH_B(pn, b_p[i]) + b_doff[i], b_src[i] + kb);
            cp_commit();
        }
        uint32_t afh[2][4], afl[2][4];
        ldm4(afh[0], smb + WH_A(p, 0) + aRow);
        ldm4(afh[1], smb + WH_A(p, 0) + aRow + 32);
        ldm4(afl[0], smb + WH_A(p, 1) + aRow);
        ldm4(afl[1], smb + WH_A(p, 1) + aRow + 32);
#pragma unroll
        for (int j = 0; j < 8; j++) {
            uint32_t bh[4], bl[4];
            ldm4(bh, smb + WH_B(p, 0) + j * 8 * (BSTR * 2) + bRow);
            ldm4(bl, smb + WH_B(p, 1) + j * 8 * (BSTR * 2) + bRow);
            mma_bf16(acc[j], afh[0], bh[0], bh[1]);
            mma_bf16(acc[j], afh[0], bl[0], bl[1]);
            mma_bf16(acc[j], afl[0], bh[0], bh[1]);
            mma_bf16(acc[j], afh[1], bh[2], bh[3]);
            mma_bf16(acc[j], afh[1], bl[2], bl[3]);
            mma_bf16(acc[j], afl[1], bh[2], bh[3]);
        }
        __syncthreads();
    }

    // ---------- fused epilogue ----------
    const int g = lane >> 2;
    const int c2 = (lane & 3) * 2;
    const int row0 = nbase + 16 * wid + g;
    const int row1 = row0 + 8;

    float* o0 = g_Wh + ((size_t)h * N_NODES + row0) * OUT_F + c2;
    float* o1 = g_Wh + ((size_t)h * N_NODES + row1) * OUT_F + c2;
#pragma unroll
    for (int j = 0; j < 8; j++) {
        *(float2*)(o0 + j * 8) = make_float2(acc[j][0], acc[j][1]);
        *(float2*)(o1 + j * 8) = make_float2(acc[j][2], acc[j][3]);
    }

    __half* T = (__half*)(sm + WH_T);
    float* av = (float*)(sm + WH_AV);
    if (t < 64) {
        av[t] = a1v[h * OUT_F + t];
        av[64 + t] = a2v[h * OUT_F + t];
    }
    const int ml0 = 16 * wid + g;
#pragma unroll
    for (int j = 0; j < 8; j++) {
        int o = c2 + j * 8;
        T[o * 136 + ml0] = __float2half(acc[j][0]);
        T[(o + 1) * 136 + ml0] = __float2half(acc[j][1]);
        T[o * 136 + ml0 + 8] = __float2half(acc[j][2]);
        T[(o + 1) * 136 + ml0 + 8] = __float2half(acc[j][3]);
    }
    __syncthreads();

#pragma unroll
    for (int i = 0; i < 4; i++) {
        int idx = t * 4 + i;
        int o = idx >> 4, q = idx & 15;
        uint4 v = *(const uint4*)(T + o * 136 + q * 8);
        *(uint4*)(g_WhT_h16 + ((size_t)h * OUT_F + o) * N_NODES + nbase + q * 8) = v;
    }

    float f10 = 0.f, f20 = 0.f, f11 = 0.f, f21 = 0.f;
#pragma unroll
    for (int j = 0; j < 8; j++) {
        int o = c2 + j * 8;
        float a1x = av[o], a1y = av[o + 1];
        float a2x = av[64 + o], a2y = av[64 + o + 1];
        f10 += acc[j][0] * a1x + acc[j][1] * a1y;
        f20 += acc[j][0] * a2x + acc[j][1] * a2y;
        f11 += acc[j][2] * a1x + acc[j][3] * a1y;
        f21 += acc[j][2] * a2x + acc[j][3] * a2y;
    }
#pragma unroll
    for (int off = 1; off <= 2; off <<= 1) {
        f10 += __shfl_xor_sync(0xffffffffu, f10, off);
        f20 += __shfl_xor_sync(0xffffffffu, f20, off);
        f11 += __shfl_xor_sync(0xffffffffu, f11, off);
        f21 += __shfl_xor_sync(0xffffffffu, f21, off);
    }
    if ((lane & 3) == 0) {
        int i0 = h * N_NODES + row0;
        int i1 = h * N_NODES + row1;
        g_f1[i0] = f10;
        g_f2[i0] = f20;
        g_P2[i0] = expf(f20);
        g_Q2[i0] = expf(ALPHA * f20);
        g_f1[i1] = f11;
        g_f2[i1] = f21;
        g_P2[i1] = expf(f21);
        g_Q2[i1] = expf(ALPHA * f21);
    }
}

// ---------------- kernel: per-head max of f2 + pack fp16 tables ----------------
__global__ __launch_bounds__(256) void maxf2_kernel() {
    __shared__ float red[256];
    const int h = blockIdx.x, t = threadIdx.x;
    float m = -3.4e38f;
#pragma unroll
    for (int i = 0; i < 16; i++) m = fmaxf(m, g_f2[h * N_NODES + t + i * 256]);
    red[t] = m;

    const int bm = h * N_NODES + t * 16;
#pragma unroll
    for (int i = 0; i < 4; i++) {
        float4 pp = *(const float4*)(g_P2 + bm + i * 4);
        float4 qq = *(const float4*)(g_Q2 + bm + i * 4);
        uint4 v;
        v.x = h2bits(__floats2half2_rn(pp.x, pp.y));
        v.y = h2bits(__floats2half2_rn(qq.x, qq.y));
        v.z = h2bits(__floats2half2_rn(pp.z, pp.w));
        v.w = h2bits(__floats2half2_rn(qq.z, qq.w));
        *(uint4*)(g_tab2 + (size_t)h * (N_NODES / 2) + t * 8 + i * 2) = v;
    }

    __syncthreads();
    for (int s = 128; s; s >>= 1) {
        if (t < s) red[t] = fmaxf(red[t], red[t + s]);
        __syncthreads();
    }
    if (t == 0) g_mx[h] = red[0];
}

// ---------------- kernel: fp16 HMMA aggregation, register-fragment A ----------------
// 128 rows x 64 cols per CTA, 256 threads / 8 warps, warp tile 32 rows x 32 cols.
// A fragments in registers (PRMT masks); each B ldmatrix feeds 8 MMAs (2 row tiles).
__global__ __launch_bounds__(256, 2) void gat_mma_kernel(float* __restrict__ out) {
    extern __shared__ __align__(16) char sm[];
    const int t = threadIdx.x;
    const int wid = t >> 5, lane = t & 31;
    const int h = blockIdx.y;
    const int nbase = blockIdx.x * GAT_RT;
    const int hN = h * N_NODES;
    const uint32_t smb = smem_u32(sm);

    const int rgrp = wid & 3;        // 32-row group
    const int chalf = wid >> 2;      // 32-col half
    const int g = lane >> 2;
    const int c2 = (lane & 3) * 2;
    const int R0 = rgrp * 32 + g;    // CTA-local rows this lane owns
    const int R1 = R0 + 8;
    const int R2 = R0 + 16;
    const int R3 = R0 + 24;

    // per-row P1/Q1 as broadcast half2 (max-shifted)
    const float mxv = g_mx[h];
    __half2 hP1[4], hQ1[4];
    {
        const int Rl[4] = {R0, R1, R2, R3};
#pragma unroll
        for (int r = 0; r < 4; r++) {
            float f1 = g_f1[hN + nbase + Rl[r]];
            float sM = f1 + mxv;
            float M = sM > 0.f ? sM : ALPHA * sM;
            hP1[r] = __half2half2(__float2half_rn(expf(f1 - M)));
            hQ1[r] = __half2half2(__float2half_rn(expf(ALPHA * f1 - M)));
        }
    }

    // B staging: 512 quads, 2 per thread
    const __half* whTh = g_WhT_h16 + ((size_t)h * OUT_F) * N_NODES;
    const __half* b_src[2];
    uint32_t b_doff[2];
#pragma unroll
    for (int i = 0; i < 2; i++) {
        int idx = t * 2 + i;
        int br = idx >> 3, bq = idx & 7;
        b_src[i] = whTh + (size_t)br * N_NODES + bq * 8;
        b_doff[i] = (uint32_t)(br * (AST2 * 2) + bq * 16);
    }

    const uint2* tab_src = g_tab2 + (size_t)h * (N_NODES / 2);
    const unsigned* adj_base = g_adjbits + (size_t)nbase * (N_NODES / 32);

    // ---- prologue: B(0), adj(0), tab(0), tab(1) ----
#pragma unroll
    for (int i = 0; i < 2; i++) cp16(smb + GB_B(0) + b_doff[i], b_src[i]);
    if (t < 128) cp8(smb + GB_ADJ(0) + t * 8, adj_base + (size_t)t * (N_NODES / 32));
    if (t < 16) {
        cp16(smb + GB_TAB(0) + t * 16, tab_src + t * 2);
        cp16(smb + GB_TAB(1) + t * 16, tab_src + 32 + t * 2);
    }
    cp_commit();

    float acc0[4][4], acc1[4][4];
#pragma unroll
    for (int j = 0; j < 4; j++)
#pragma unroll
        for (int e = 0; e < 4; e++) {
            acc0[j][e] = 0.f;
            acc1[j][e] = 0.f;
        }
    float acc_d0[4] = {0.f, 0.f, 0.f, 0.f};
    float acc_d1[4] = {0.f, 0.f, 0.f, 0.f};

    const int jbase = chalf * 32;
    const uint32_t bOff = (jbase + (lane & 7)) * (AST2 * 2) + (lane >> 3) * 16;
    const uint32_t ONE2 = 0x3C003C00u;

    for (int c = 0; c < NCH2; c++) {
        const int p = c & 1, pn = p ^ 1;
        cp_wait<0>();
        __syncthreads();

        if (c + 1 < NCH2) {
#pragma unroll
            for (int i = 0; i < 2; i++)
                cp16(smb + GB_B(pn) + b_doff[i], b_src[i] + (c + 1) * KC2);
            if (t < 128)
                cp8(smb + GB_ADJ(pn) + t * 8,
                    adj_base + (size_t)t * (N_NODES / 32) + (c + 1) * 2);
            if (c + 2 < NCH2 && t < 16)
                cp16(smb + GB_TAB((c + 2) % 3) + t * 16, tab_src + (c + 2) * 32 + t * 2);
            cp_commit();
        }

        // ---- per-row adjacency words, shifted for PRMT ----
        unsigned lo[4][2], hi[4][2];
        {
            const int Rl[4] = {R0, R1, R2, R3};
#pragma unroll
            for (int r = 0; r < 4; r++) {
                uint2 aw = *(const uint2*)(sm + GB_ADJ(p) + Rl[r] * 8);
                unsigned tx = aw.x >> c2, ty = aw.y >> c2;
                lo[r][0] = tx << 7;
                hi[r][0] = tx << 6;
                lo[r][1] = ty << 7;
                hi[r][1] = ty << 6;
            }
        }
        const char* tabp = sm + GB_TAB(c % 3) + (lane & 3) * 8;

        uint32_t af0[4][4], af1[4][4];
#pragma unroll
        for (int s = 0; s < 4; s++) {
            const int wsel = s >> 1;
#pragma unroll
            for (int d = 0; d < 2; d++) {
                const int k = 2 * (s & 1) + d;
                const unsigned sel = 0xCC88u + 0x1111u * (unsigned)k;
                uint2 pq = *(const uint2*)(tabp + (8 * s + 4 * d) * 8);
                __half2 P2 = *reinterpret_cast<__half2*>(&pq.x);
                __half2 Q2 = *reinterpret_cast<__half2*>(&pq.y);
                __half2 w0 = __hmax2(__hmul2(hP1[0], P2), __hmul2(hQ1[0], Q2));
                __half2 w1 = __hmax2(__hmul2(hP1[1], P2), __hmul2(hQ1[1], Q2));
                __half2 w2 = __hmax2(__hmul2(hP1[2], P2), __hmul2(hQ1[2], Q2));
                __half2 w3 = __hmax2(__hmul2(hP1[3], P2), __hmul2(hQ1[3], Q2));
                af0[s][2 * d] = h2bits(w0) & prmt(lo[0][wsel], hi[0][wsel], sel);
                af0[s][2 * d + 1] = h2bits(w1) & prmt(lo[1][wsel], hi[1][wsel], sel);
                af1[s][2 * d] = h2bits(w2) & prmt(lo[2][wsel], hi[2][wsel], sel);
                af1[s][2 * d + 1] = h2bits(w3) & prmt(lo[3][wsel], hi[3][wsel], sel);
            }
        }

        // ---- MMA on B buffer p: each B ldm4 feeds both row tiles ----
#pragma unroll
        for (int j = 0; j < 4; j++) {
            uint32_t b0[4], b1[4];
            const uint32_t bj = smb + GB_B(p) + j * 8 * (AST2 * 2) + bOff;
            ldm4(b0, bj);
            ldm4(b1, bj + 64);
            mma_f16(acc0[j], af0[0], b0[0], b0[1]);
            mma_f16(acc1[j], af1[0], b0[0], b0[1]);
            mma_f16(acc0[j], af0[1], b0[2], b0[3]);
            mma_f16(acc1[j], af1[1], b0[2], b0[3]);
            mma_f16(acc0[j], af0[2], b1[0], b1[1]);
            mma_f16(acc1[j], af1[2], b1[0], b1[1]);
            mma_f16(acc0[j], af0[3], b1[2], b1[3]);
            mma_f16(acc1[j], af1[3], b1[2], b1[3]);
        }
        mma_f16(acc_d0, af0[0], ONE2, ONE2);
        mma_f16(acc_d1, af1[0], ONE2, ONE2);
        mma_f16(acc_d0, af0[1], ONE2, ONE2);
        mma_f16(acc_d1, af1[1], ONE2, ONE2);
        mma_f16(acc_d0, af0[2], ONE2, ONE2);
        mma_f16(acc_d1, af1[2], ONE2, ONE2);
        mma_f16(acc_d0, af0[3], ONE2, ONE2);
        mma_f16(acc_d1, af1[3], ONE2, ONE2);
    }

    // ---- epilogue: 4 rows per lane ----
    const float inv0 = 1.0f / acc_d0[0];
    const float inv1 = 1.0f / acc_d0[2];
    const float inv2 = 1.0f / acc_d1[0];
    const float inv3 = 1.0f / acc_d1[2];
    float* o0 = out + (size_t)(nbase + R0) * (HEADS * OUT_F) + h * OUT_F + jbase + c2;
    float* o1 = out + (size_t)(nbase + R1) * (HEADS * OUT_F) + h * OUT_F + jbase + c2;
    float* o2 = out + (size_t)(nbase + R2) * (HEADS * OUT_F) + h * OUT_F + jbase + c2;
    float* o3 = out + (size_t)(nbase + R3) * (HEADS * OUT_F) + h * OUT_F + jbase + c2;
#pragma unroll
    for (int j = 0; j < 4; j++) {
        *(float2*)(o0 + j * 8) = make_float2(acc0[j][0] * inv0, acc0[j][1] * inv0);
        *(float2*)(o1 + j * 8) = make_float2(acc0[j][2] * inv1, acc0[j][3] * inv1);
        *(float2*)(o2 + j * 8) = make_float2(acc1[j][0] * inv2, acc1[j][1] * inv2);
        *(float2*)(o3 + j * 8) = make_float2(acc1[j][2] * inv3, acc1[j][3] * inv3);
    }
}

// ---------------- launch ----------------
extern "C" void kernel_launch(void* const* d_in, const int* in_sizes, int n_in,
                              void* d_out, int out_size) {
    const float* x   = (const float*)d_in[0];
    const int*   adj = (const int*)d_in[1];
    const float* W   = (const float*)d_in[2];
    const float* a1  = (const float*)d_in[3];
    const float* a2  = (const float*)d_in[4];
    float* out = (float*)d_out;

    cudaFuncSetAttribute(wh_mma_kernel, cudaFuncAttributeMaxDynamicSharedMemorySize,
                         WH_SMEM);
    cudaFuncSetAttribute(gat_mma_kernel, cudaFuncAttributeMaxDynamicSharedMemorySize,
                         GB_SMEM);

    prep_kernel<<<3080, 256>>>(adj, x, W);

    dim3 gW(N_NODES / RT, HEADS);
    wh_mma_kernel<<<gW, 256, WH_SMEM>>>(a1, a2);

    maxf2_kernel<<<HEADS, 256>>>();

    dim3 gD(N_NODES / GAT_RT, HEADS);
    gat_mma_kernel<<<gD, 256, GB_SMEM>>>(out);
}